// round 7
// baseline (speedup 1.0000x reference)
#include <cuda_runtime.h>
#include <cuda_fp16.h>
#include <math.h>
#include <stdint.h>

// Problem constants
#define BATCH   4
#define SEQLEN  2048
#define DMODEL  512
#define DSTATE  64
#define MTOT    (BATCH * SEQLEN)   // 8192

// ---------------------------------------------------------------------------
// Device scratch (no cudaMalloc allowed)
// ---------------------------------------------------------------------------
__device__ float  g_u[BATCH * DMODEL * SEQLEN];   // [b][d][l] fp32 (scan input)
__device__ __half g_yh[BATCH * DMODEL * SEQLEN];  // [b][d][l] y hi
__device__ __half g_yl[BATCH * DMODEL * SEQLEN];  // [b][d][l] y lo
__device__ __half g_ah[MTOT * DMODEL];            // x hi [token][k]
__device__ __half g_al[MTOT * DMODEL];            // x lo [token][k]
__device__ __half g_wh[2 * DMODEL * DMODEL];      // W_in | W_out hi
__device__ __half g_wl[2 * DMODEL * DMODEL];      // W_in | W_out lo

// ---------------------------------------------------------------------------
// PTX helpers
// ---------------------------------------------------------------------------
__device__ __forceinline__ uint32_t smem_u32(const void* p) {
    uint32_t a;
    asm("{ .reg .u64 t; cvta.to.shared.u64 t, %1; cvt.u32.u64 %0, t; }" : "=r"(a) : "l"(p));
    return a;
}
__device__ __forceinline__ void cpasync16(uint32_t s, const void* g) {
    asm volatile("cp.async.cg.shared.global [%0], [%1], 16;" :: "r"(s), "l"(g));
}
__device__ __forceinline__ void cp_commit() {
    asm volatile("cp.async.commit_group;" ::: "memory");
}
__device__ __forceinline__ void ldsm4(uint32_t a, uint32_t* r) {
    asm volatile("ldmatrix.sync.aligned.m8n8.x4.shared.b16 {%0,%1,%2,%3}, [%4];"
                 : "=r"(r[0]), "=r"(r[1]), "=r"(r[2]), "=r"(r[3]) : "r"(a));
}
__device__ __forceinline__ void ldsm4t(uint32_t a, uint32_t* r) {
    asm volatile("ldmatrix.sync.aligned.m8n8.x4.trans.shared.b16 {%0,%1,%2,%3}, [%4];"
                 : "=r"(r[0]), "=r"(r[1]), "=r"(r[2]), "=r"(r[3]) : "r"(a));
}
__device__ __forceinline__ void mma16816(float* c, const uint32_t* a, const uint32_t* b) {
    asm volatile(
        "mma.sync.aligned.m16n8k16.row.col.f32.f16.f16.f32 "
        "{%0,%1,%2,%3}, {%4,%5,%6,%7}, {%8,%9}, {%0,%1,%2,%3};"
        : "+f"(c[0]), "+f"(c[1]), "+f"(c[2]), "+f"(c[3])
        : "r"(a[0]), "r"(a[1]), "r"(a[2]), "r"(a[3]), "r"(b[0]), "r"(b[1]));
}

// ---------------------------------------------------------------------------
// Merged split-precision conversion for x, W_in, W_out (one launch)
// ---------------------------------------------------------------------------
#define N4_X (MTOT * DMODEL / 4)
#define N4_W (DMODEL * DMODEL / 4)

__global__ __launch_bounds__(256) void convert_all(const float* __restrict__ x,
                                                   const float* __restrict__ w_in,
                                                   const float* __restrict__ w_out,
                                                   __half* __restrict__ ah,
                                                   __half* __restrict__ al,
                                                   __half* __restrict__ wh,
                                                   __half* __restrict__ wl)
{
    int i = blockIdx.x * 256 + threadIdx.x;
    const float* src;
    __half *dh, *dl;
    int off;
    if (i < N4_X) {
        src = x; dh = ah; dl = al; off = i;
    } else if (i < N4_X + N4_W) {
        src = w_in; dh = wh; dl = wl; off = i - N4_X;
    } else if (i < N4_X + 2 * N4_W) {
        src = w_out; dh = wh + DMODEL * DMODEL; dl = wl + DMODEL * DMODEL;
        off = i - N4_X - N4_W;
    } else return;

    float4 v = ((const float4*)src)[off];
    __half h0 = __float2half_rn(v.x);
    __half h1 = __float2half_rn(v.y);
    __half h2 = __float2half_rn(v.z);
    __half h3 = __float2half_rn(v.w);
    __half l0 = __float2half_rn(v.x - __half2float(h0));
    __half l1 = __float2half_rn(v.y - __half2float(h1));
    __half l2 = __float2half_rn(v.z - __half2float(h2));
    __half l3 = __float2half_rn(v.w - __half2float(h3));
    uint2 ph, pl;
    ph.x = (uint32_t)__half_as_ushort(h0) | ((uint32_t)__half_as_ushort(h1) << 16);
    ph.y = (uint32_t)__half_as_ushort(h2) | ((uint32_t)__half_as_ushort(h3) << 16);
    pl.x = (uint32_t)__half_as_ushort(l0) | ((uint32_t)__half_as_ushort(l1) << 16);
    pl.y = (uint32_t)__half_as_ushort(l2) | ((uint32_t)__half_as_ushort(l3) << 16);
    ((uint2*)dh)[off] = ph;
    ((uint2*)dl)[off] = pl;
}

// ---------------------------------------------------------------------------
// GEMM common config
// ---------------------------------------------------------------------------
#define STAGE_BYTES 65536            // 4 arrays x 16 KB
#define NSTAGE 3
#define SMEM_BYTES (NSTAGE * STAGE_BYTES)
#define NTHREADS 512

// ---------------------------------------------------------------------------
// GEMM1 (in_proj): D[d, token] = sum_k W_in[d,k] * x[token,k]; 16 warps 4x4,
// warp tile 32x32, 3-stage cp.async, split-fp16 3-pass. Epilogue -> g_u[b][d][l].
// ---------------------------------------------------------------------------
__global__ __launch_bounds__(NTHREADS, 1) void gemm_mma1(const __half* __restrict__ Abase_h,
                                                         const __half* __restrict__ Abase_l,
                                                         const __half* __restrict__ Bbase_h,
                                                         const __half* __restrict__ Bbase_l,
                                                         const float* __restrict__ bias)
{
    extern __shared__ __align__(1024) char dyn[];
    const uint32_t sb = smem_u32(dyn);
    const int tid  = threadIdx.x;
    const int wid  = tid >> 5;
    const int lane = tid & 31;
    const int wm = wid & 3;
    const int wn = wid >> 2;
    const int n0 = blockIdx.x * 128;   // token
    const int m0 = blockIdx.y * 128;   // d

    const __half* Ah = Abase_h + (size_t)m0 * 512;
    const __half* Al = Abase_l + (size_t)m0 * 512;
    const __half* Bh = Bbase_h + (size_t)n0 * 512;
    const __half* Bl = Bbase_l + (size_t)n0 * 512;

    auto load_stage = [&](int stage, int c) {
        const int k0 = c * 64;
        const uint32_t sbase = sb + stage * STAGE_BYTES;
#pragma unroll
        for (int i = 0; i < 2; i++) {
            const int idx = i * NTHREADS + tid;
            const int r  = idx >> 3;
            const int ch = idx & 7;
            const uint32_t so = (uint32_t)((r * 128 + ch * 16) ^ ((r & 7) << 4));
            const size_t go = (size_t)r * 512 + k0 + ch * 8;
            cpasync16(sbase + so,         Ah + go);
            cpasync16(sbase + 16384 + so, Al + go);
            cpasync16(sbase + 32768 + so, Bh + go);
            cpasync16(sbase + 49152 + so, Bl + go);
        }
        cp_commit();
    };

    float c[2][4][4];
#pragma unroll
    for (int mi = 0; mi < 2; mi++)
#pragma unroll
        for (int ni = 0; ni < 4; ni++)
#pragma unroll
            for (int j = 0; j < 4; j++) c[mi][ni][j] = 0.0f;

    load_stage(0, 0);
    load_stage(1, 1);

    const int grp = lane >> 3;
    const int sub = lane & 7;

#pragma unroll 1
    for (int cch = 0; cch < 8; cch++) {
        if (cch == 7) asm volatile("cp.async.wait_group 0;" ::: "memory");
        else          asm volatile("cp.async.wait_group 1;" ::: "memory");
        __syncthreads();
        if (cch + 2 < 8) load_stage((cch + 2) % NSTAGE, cch + 2);

        const uint32_t sa = sb + (cch % NSTAGE) * STAGE_BYTES;

#pragma unroll
        for (int s = 0; s < 4; s++) {
            uint32_t aH[2][4], aL[2][4], bH[2][4], bL[2][4];
#pragma unroll
            for (int mi = 0; mi < 2; mi++) {
                const int rowA = wm * 32 + mi * 16 + (grp & 1) * 8 + sub;
                const int kbA  = s * 32 + (grp >> 1) * 16;   // bytes
                const uint32_t off = (uint32_t)((rowA * 128 + kbA) ^ ((rowA & 7) << 4));
                ldsm4(sa + off,         aH[mi]);
                ldsm4(sa + 16384 + off, aL[mi]);
            }
#pragma unroll
            for (int p = 0; p < 2; p++) {
                const int atom = 2 * p + (grp >> 1);
                const int rowB = wn * 32 + atom * 8 + sub;
                const int kbB  = s * 32 + (grp & 1) * 16;    // bytes
                const uint32_t off = (uint32_t)((rowB * 128 + kbB) ^ ((rowB & 7) << 4));
                ldsm4(sa + 32768 + off, bH[p]);
                ldsm4(sa + 49152 + off, bL[p]);
            }
#pragma unroll
            for (int mi = 0; mi < 2; mi++)
#pragma unroll
                for (int p = 0; p < 2; p++) {
                    mma16816(c[mi][2 * p + 0], aH[mi], &bH[p][0]);
                    mma16816(c[mi][2 * p + 1], aH[mi], &bH[p][2]);
                    mma16816(c[mi][2 * p + 0], aH[mi], &bL[p][0]);
                    mma16816(c[mi][2 * p + 1], aH[mi], &bL[p][2]);
                    mma16816(c[mi][2 * p + 0], aL[mi], &bH[p][0]);
                    mma16816(c[mi][2 * p + 1], aL[mi], &bH[p][2]);
                }
        }
    }

    // epilogue: m=d rows, n=token cols -> g_u[b][d][l]
    const int q  = lane >> 2;
    const int t2 = (lane & 3) * 2;
    const int b  = n0 >> 11;
    const int lt = (n0 & 2047) + wn * 32;
#pragma unroll
    for (int mi = 0; mi < 2; mi++)
#pragma unroll
        for (int rr = 0; rr < 2; rr++) {
            const int d_row = m0 + wm * 32 + mi * 16 + rr * 8 + q;
            const float bi = __ldg(bias + d_row);
            float* dst = g_u + ((size_t)(b * DMODEL + d_row) << 11) + lt;
#pragma unroll
            for (int ni = 0; ni < 4; ni++) {
                float2 v;
                v.x = c[mi][ni][rr * 2 + 0] + bi;
                v.y = c[mi][ni][rr * 2 + 1] + bi;
                *(float2*)(dst + ni * 8 + t2) = v;
            }
        }
}

// ---------------------------------------------------------------------------
// GEMM2 (out_proj): out[token, n] = sum_k y[token,k] * W_out[n,k]
// A = y read DIRECTLY from K-major [b][d][l] fp16 hi/lo via ldmatrix.trans.
// A smem tile: [64 k][128 m] halves, 256B rows, chunk-XOR swizzle.
// B = W_out row-major, standard path. 3-pass split. Epilogue -> out row-major.
// ---------------------------------------------------------------------------
__global__ __launch_bounds__(NTHREADS, 1) void gemm_mma2(const __half* __restrict__ Wh,
                                                         const __half* __restrict__ Wl,
                                                         const float* __restrict__ bias,
                                                         float* __restrict__ Cout)
{
    extern __shared__ __align__(1024) char dyn[];
    const uint32_t sb = smem_u32(dyn);
    const int tid  = threadIdx.x;
    const int wid  = tid >> 5;
    const int lane = tid & 31;
    const int wm = wid & 3;
    const int wn = wid >> 2;
    const int n0 = blockIdx.x * 128;   // d_out
    const int m0 = blockIdx.y * 128;   // token
    const int b    = m0 >> 11;
    const int ltok = m0 & 2047;

    const __half* Bh = Wh + (size_t)n0 * 512;
    const __half* Bl = Wl + (size_t)n0 * 512;

    auto load_stage = [&](int stage, int c) {
        const int k0 = c * 64;         // d-offset for A, k-offset for B
        const uint32_t sbase = sb + stage * STAGE_BYTES;
#pragma unroll
        for (int i = 0; i < 2; i++) {
            const int idx = i * NTHREADS + tid;
            // A: [64 rows(k=d)][16 chunks of 16B (m=token)]
            const int rA  = idx >> 4;
            const int chA = idx & 15;
            const uint32_t soA = (uint32_t)(rA * 256 + ((chA ^ (rA & 7)) << 4));
            const size_t  goA = ((size_t)(b * DMODEL + k0 + rA) << 11) + ltok + chA * 8;
            cpasync16(sbase + soA,         g_yh + goA);
            cpasync16(sbase + 16384 + soA, g_yl + goA);
            // B: [128 rows(n)][8 chunks of 16B (k)]
            const int rB  = idx >> 3;
            const int chB = idx & 7;
            const uint32_t soB = (uint32_t)((rB * 128 + chB * 16) ^ ((rB & 7) << 4));
            const size_t  goB = (size_t)rB * 512 + k0 + chB * 8;
            cpasync16(sbase + 32768 + soB, Bh + goB);
            cpasync16(sbase + 49152 + soB, Bl + goB);
        }
        cp_commit();
    };

    float c[2][4][4];
#pragma unroll
    for (int mi = 0; mi < 2; mi++)
#pragma unroll
        for (int ni = 0; ni < 4; ni++)
#pragma unroll
            for (int j = 0; j < 4; j++) c[mi][ni][j] = 0.0f;

    load_stage(0, 0);
    load_stage(1, 1);

    const int grp = lane >> 3;
    const int sub = lane & 7;

#pragma unroll 1
    for (int cch = 0; cch < 8; cch++) {
        if (cch == 7) asm volatile("cp.async.wait_group 0;" ::: "memory");
        else          asm volatile("cp.async.wait_group 1;" ::: "memory");
        __syncthreads();
        if (cch + 2 < 8) load_stage((cch + 2) % NSTAGE, cch + 2);

        const uint32_t sa = sb + (cch % NSTAGE) * STAGE_BYTES;

#pragma unroll
        for (int s = 0; s < 4; s++) {
            uint32_t aH[2][4], aL[2][4], bH[2][4], bL[2][4];
            // A fragments via ldmatrix.trans from [k][m] tile:
            // mats: (m0,k0)=lanes0-7, (m8,k0)=8-15, (m0,k8)=16-23, (m8,k8)=24-31
            // lane -> k_row = s*16 + (grp>>1)*8 + sub ; m_col = base + (grp&1)*8
#pragma unroll
            for (int mi = 0; mi < 2; mi++) {
                const int krow = s * 16 + (grp >> 1) * 8 + sub;
                const int mcol = wm * 32 + mi * 16 + (grp & 1) * 8;
                const int chunk = mcol >> 3;
                const uint32_t off = (uint32_t)(krow * 256 + ((chunk ^ (krow & 7)) << 4));
                ldsm4t(sa + off,         aH[mi]);
                ldsm4t(sa + 16384 + off, aL[mi]);
            }
#pragma unroll
            for (int p = 0; p < 2; p++) {
                const int atom = 2 * p + (grp >> 1);
                const int rowB = wn * 32 + atom * 8 + sub;
                const int kbB  = s * 32 + (grp & 1) * 16;    // bytes
                const uint32_t off = (uint32_t)((rowB * 128 + kbB) ^ ((rowB & 7) << 4));
                ldsm4(sa + 32768 + off, bH[p]);
                ldsm4(sa + 49152 + off, bL[p]);
            }
#pragma unroll
            for (int mi = 0; mi < 2; mi++)
#pragma unroll
                for (int p = 0; p < 2; p++) {
                    mma16816(c[mi][2 * p + 0], aH[mi], &bH[p][0]);
                    mma16816(c[mi][2 * p + 1], aH[mi], &bH[p][2]);
                    mma16816(c[mi][2 * p + 0], aH[mi], &bL[p][0]);
                    mma16816(c[mi][2 * p + 1], aH[mi], &bL[p][2]);
                    mma16816(c[mi][2 * p + 0], aL[mi], &bH[p][0]);
                    mma16816(c[mi][2 * p + 1], aL[mi], &bH[p][2]);
                }
        }
    }

    // epilogue: row-major out
    const int q  = lane >> 2;
    const int t2 = (lane & 3) * 2;
#pragma unroll
    for (int mi = 0; mi < 2; mi++)
#pragma unroll
        for (int rr = 0; rr < 2; rr++) {
            const int row = m0 + wm * 32 + mi * 16 + rr * 8 + q;
            float* dst = Cout + (size_t)row * 512 + n0 + wn * 32;
#pragma unroll
            for (int ni = 0; ni < 4; ni++) {
                const float2 bv = *(const float2*)(bias + n0 + wn * 32 + ni * 8 + t2);
                float2 v;
                v.x = c[mi][ni][rr * 2 + 0] + bv.x;
                v.y = c[mi][ni][rr * 2 + 1] + bv.y;
                *(float2*)(dst + ni * 8 + t2) = v;
            }
        }
}

// ---------------------------------------------------------------------------
// SSM recurrence scan: one warp per (b,d); 2 states/lane.
// Writes y as fp16 hi/lo pairs in [b][d][l] (consumed by gemm_mma2 via trans).
// ---------------------------------------------------------------------------
__global__ __launch_bounds__(256) void s4_scan(const float* __restrict__ A_log,
                                               const float* __restrict__ Bp,
                                               const float* __restrict__ Cp,
                                               const float* __restrict__ Dp,
                                               const float* __restrict__ dt)
{
    const int warp = (blockIdx.x * blockDim.x + threadIdx.x) >> 5;
    const int lane = threadIdx.x & 31;
    const int d = warp & (DMODEL - 1);
    const int b = warp >> 9;

    const float dtd = dt[d];
    const int i0 = d * DSTATE + lane;
    const int i1 = i0 + 32;

    const float r0 = expf(-expf(A_log[i0]) * dtd);
    const float r1 = expf(-expf(A_log[i1]) * dtd);
    const float c0 = Cp[i0] * Bp[i0] * dtd;
    const float c1 = Cp[i1] * Bp[i1] * dtd;
    const float Dd = Dp[d];

    const size_t rowoff = (size_t)(b * DMODEL + d) << 11;
    const float* ub = g_u + rowoff;
    __half* yh = g_yh + rowoff;
    __half* yl = g_yl + rowoff;

    float z0 = 0.0f, z1 = 0.0f;

    for (int t0 = 0; t0 < SEQLEN; t0 += 32) {
        const float uv = ub[t0 + lane];
        float p[32];
#pragma unroll
        for (int i = 0; i < 32; i++) {
            const float uu = __shfl_sync(0xffffffffu, uv, i);
            z0 = fmaf(r0, z0, uu);
            z1 = fmaf(r1, z1, uu);
            p[i] = fmaf(c0, z0, c1 * z1);
        }
        const bool h16 = (lane & 16);
        float s16[16];
#pragma unroll
        for (int k = 0; k < 16; k++) {
            const float keep = h16 ? p[k + 16] : p[k];
            const float send = h16 ? p[k] : p[k + 16];
            s16[k] = keep + __shfl_xor_sync(0xffffffffu, send, 16);
        }
        const bool h8 = (lane & 8);
        float s8[8];
#pragma unroll
        for (int k = 0; k < 8; k++) {
            const float keep = h8 ? s16[k + 8] : s16[k];
            const float send = h8 ? s16[k] : s16[k + 8];
            s8[k] = keep + __shfl_xor_sync(0xffffffffu, send, 8);
        }
        const bool h4 = (lane & 4);
        float s4[4];
#pragma unroll
        for (int k = 0; k < 4; k++) {
            const float keep = h4 ? s8[k + 4] : s8[k];
            const float send = h4 ? s8[k] : s8[k + 4];
            s4[k] = keep + __shfl_xor_sync(0xffffffffu, send, 4);
        }
        const bool h2 = (lane & 2);
        float s2[2];
#pragma unroll
        for (int k = 0; k < 2; k++) {
            const float keep = h2 ? s4[k + 2] : s4[k];
            const float send = h2 ? s4[k] : s4[k + 2];
            s2[k] = keep + __shfl_xor_sync(0xffffffffu, send, 2);
        }
        const bool h1 = (lane & 1);
        const float keep = h1 ? s2[1] : s2[0];
        const float send = h1 ? s2[0] : s2[1];
        const float tot = keep + __shfl_xor_sync(0xffffffffu, send, 1);

        const float yv = fmaf(Dd, uv, tot);
        const __half hv = __float2half_rn(yv);
        yh[t0 + lane] = hv;
        yl[t0 + lane] = __float2half_rn(yv - __half2float(hv));
    }
}

// ---------------------------------------------------------------------------
extern "C" void kernel_launch(void* const* d_in, const int* in_sizes, int n_in,
                              void* d_out, int out_size)
{
    const float* x     = (const float*)d_in[0];
    const float* W_in  = (const float*)d_in[1];
    const float* b_in  = (const float*)d_in[2];
    const float* A_log = (const float*)d_in[3];
    const float* B     = (const float*)d_in[4];
    const float* C     = (const float*)d_in[5];
    const float* D     = (const float*)d_in[6];
    const float* dt    = (const float*)d_in[7];
    const float* W_out = (const float*)d_in[8];
    const float* b_out = (const float*)d_in[9];
    float* out = (float*)d_out;

    static bool attr_done = false;
    if (!attr_done) {
        cudaFuncSetAttribute(gemm_mma1, cudaFuncAttributeMaxDynamicSharedMemorySize, SMEM_BYTES);
        cudaFuncSetAttribute(gemm_mma2, cudaFuncAttributeMaxDynamicSharedMemorySize, SMEM_BYTES);
        attr_done = true;
    }

    __half *p_ah, *p_al, *p_wh, *p_wl;
    cudaGetSymbolAddress((void**)&p_ah, g_ah);
    cudaGetSymbolAddress((void**)&p_al, g_al);
    cudaGetSymbolAddress((void**)&p_wh, g_wh);
    cudaGetSymbolAddress((void**)&p_wl, g_wl);

    // 1) split-convert x + W_in + W_out (single launch)
    {
        const int total = N4_X + 2 * N4_W;
        convert_all<<<(total + 255) / 256, 256>>>(x, W_in, W_out, p_ah, p_al, p_wh, p_wl);
    }

    // 2) in_proj: D[d, token] -> g_u[b][d][l]
    {
        dim3 g(MTOT / 128, DMODEL / 128);   // (64, 4)
        gemm_mma1<<<g, NTHREADS, SMEM_BYTES>>>(p_wh, p_wl, p_ah, p_al, b_in);
    }

    // 3) SSM recurrence: g_u -> g_yh/g_yl  [b][d][l] fp16 hi/lo
    s4_scan<<<(BATCH * DMODEL) / 8, 256>>>(A_log, B, C, D, dt);

    // 4) out_proj: y (K-major, via ldmatrix.trans) @ W_out^T -> out
    {
        dim3 g(DMODEL / 128, MTOT / 128);   // (4, 64)
        gemm_mma2<<<g, NTHREADS, SMEM_BYTES>>>(p_wh + DMODEL * DMODEL,
                                               p_wl + DMODEL * DMODEL, b_out, out);
    }
}

// round 8
// speedup vs baseline: 1.0548x; 1.0548x over previous
#include <cuda_runtime.h>
#include <cuda_fp16.h>
#include <math.h>
#include <stdint.h>

// Problem constants
#define BATCH   4
#define SEQLEN  2048
#define DMODEL  512
#define DSTATE  64
#define MTOT    (BATCH * SEQLEN)   // 8192

// ---------------------------------------------------------------------------
// Device scratch (no cudaMalloc allowed)
// ---------------------------------------------------------------------------
__device__ float  g_u[BATCH * DMODEL * SEQLEN];   // [b][d][l] fp32 (scan input)
__device__ __half g_yh[BATCH * DMODEL * SEQLEN];  // [b][d][l] y hi
__device__ __half g_yl[BATCH * DMODEL * SEQLEN];  // [b][d][l] y lo
__device__ __half g_ah[MTOT * DMODEL];            // x hi [token][k]
__device__ __half g_al[MTOT * DMODEL];            // x lo [token][k]
__device__ __half g_wh[2 * DMODEL * DMODEL];      // W_in | W_out hi
__device__ __half g_wl[2 * DMODEL * DMODEL];      // W_in | W_out lo

// ---------------------------------------------------------------------------
// PTX helpers
// ---------------------------------------------------------------------------
__device__ __forceinline__ uint32_t smem_u32(const void* p) {
    uint32_t a;
    asm("{ .reg .u64 t; cvta.to.shared.u64 t, %1; cvt.u32.u64 %0, t; }" : "=r"(a) : "l"(p));
    return a;
}
__device__ __forceinline__ void cpasync16(uint32_t s, const void* g) {
    asm volatile("cp.async.cg.shared.global [%0], [%1], 16;" :: "r"(s), "l"(g));
}
__device__ __forceinline__ void cp_commit() {
    asm volatile("cp.async.commit_group;" ::: "memory");
}
__device__ __forceinline__ void ldsm4(uint32_t a, uint32_t* r) {
    asm volatile("ldmatrix.sync.aligned.m8n8.x4.shared.b16 {%0,%1,%2,%3}, [%4];"
                 : "=r"(r[0]), "=r"(r[1]), "=r"(r[2]), "=r"(r[3]) : "r"(a));
}
__device__ __forceinline__ void ldsm4t(uint32_t a, uint32_t* r) {
    asm volatile("ldmatrix.sync.aligned.m8n8.x4.trans.shared.b16 {%0,%1,%2,%3}, [%4];"
                 : "=r"(r[0]), "=r"(r[1]), "=r"(r[2]), "=r"(r[3]) : "r"(a));
}
__device__ __forceinline__ void mma16816(float* c, const uint32_t* a, const uint32_t* b) {
    asm volatile(
        "mma.sync.aligned.m16n8k16.row.col.f32.f16.f16.f32 "
        "{%0,%1,%2,%3}, {%4,%5,%6,%7}, {%8,%9}, {%0,%1,%2,%3};"
        : "+f"(c[0]), "+f"(c[1]), "+f"(c[2]), "+f"(c[3])
        : "r"(a[0]), "r"(a[1]), "r"(a[2]), "r"(a[3]), "r"(b[0]), "r"(b[1]));
}

// ---------------------------------------------------------------------------
// Merged split-precision conversion for x, W_in, W_out (one launch)
// ---------------------------------------------------------------------------
#define N4_X (MTOT * DMODEL / 4)
#define N4_W (DMODEL * DMODEL / 4)

__global__ __launch_bounds__(256) void convert_all(const float* __restrict__ x,
                                                   const float* __restrict__ w_in,
                                                   const float* __restrict__ w_out,
                                                   __half* __restrict__ ah,
                                                   __half* __restrict__ al,
                                                   __half* __restrict__ wh,
                                                   __half* __restrict__ wl)
{
    int i = blockIdx.x * 256 + threadIdx.x;
    const float* src;
    __half *dh, *dl;
    int off;
    if (i < N4_X) {
        src = x; dh = ah; dl = al; off = i;
    } else if (i < N4_X + N4_W) {
        src = w_in; dh = wh; dl = wl; off = i - N4_X;
    } else if (i < N4_X + 2 * N4_W) {
        src = w_out; dh = wh + DMODEL * DMODEL; dl = wl + DMODEL * DMODEL;
        off = i - N4_X - N4_W;
    } else return;

    float4 v = ((const float4*)src)[off];
    __half h0 = __float2half_rn(v.x);
    __half h1 = __float2half_rn(v.y);
    __half h2 = __float2half_rn(v.z);
    __half h3 = __float2half_rn(v.w);
    __half l0 = __float2half_rn(v.x - __half2float(h0));
    __half l1 = __float2half_rn(v.y - __half2float(h1));
    __half l2 = __float2half_rn(v.z - __half2float(h2));
    __half l3 = __float2half_rn(v.w - __half2float(h3));
    uint2 ph, pl;
    ph.x = (uint32_t)__half_as_ushort(h0) | ((uint32_t)__half_as_ushort(h1) << 16);
    ph.y = (uint32_t)__half_as_ushort(h2) | ((uint32_t)__half_as_ushort(h3) << 16);
    pl.x = (uint32_t)__half_as_ushort(l0) | ((uint32_t)__half_as_ushort(l1) << 16);
    pl.y = (uint32_t)__half_as_ushort(l2) | ((uint32_t)__half_as_ushort(l3) << 16);
    ((uint2*)dh)[off] = ph;
    ((uint2*)dl)[off] = pl;
}

// ---------------------------------------------------------------------------
// GEMM config: CTA tile 128(M) x 256(N), K-chunk 64, 2 stages.
// Stage layout: Ah@0 (16KB), Al@16K, Bh@32K (32KB), Bl@64K -> 96KB/stage.
// 16 warps in 4(M) x 4(N); warp tile 32x64. Single wave: grid = 128 CTAs.
// ---------------------------------------------------------------------------
#define STAGE_BYTES 98304
#define SMEM_BYTES  (2 * STAGE_BYTES)   // 192 KB
#define NTHREADS    512

// ---------------------------------------------------------------------------
// GEMM1 (in_proj): D[d, token] = sum_k W_in[d,k] * x[token,k]
// A = W_in rows (128), B = x rows (256 tokens). Epilogue -> g_u[b][d][l].
// ---------------------------------------------------------------------------
__global__ __launch_bounds__(NTHREADS, 1) void gemm_mma1(const __half* __restrict__ Wh,
                                                         const __half* __restrict__ Wl,
                                                         const __half* __restrict__ Xh,
                                                         const __half* __restrict__ Xl,
                                                         const float* __restrict__ bias)
{
    extern __shared__ __align__(1024) char dyn[];
    const uint32_t sb = smem_u32(dyn);
    const int tid  = threadIdx.x;
    const int wid  = tid >> 5;
    const int lane = tid & 31;
    const int wm = wid & 3;          // 4 M-groups of 32 rows
    const int wn = wid >> 2;         // 4 N-groups of 64 cols
    const int n0 = blockIdx.x * 256; // token
    const int m0 = blockIdx.y * 128; // d

    const __half* Ah = Wh + (size_t)m0 * 512;
    const __half* Al = Wl + (size_t)m0 * 512;
    const __half* Bh = Xh + (size_t)n0 * 512;
    const __half* Bl = Xl + (size_t)n0 * 512;

    auto load_stage = [&](int stage, int c) {
        const int k0 = c * 64;
        const uint32_t sbase = sb + stage * STAGE_BYTES;
#pragma unroll
        for (int i = 0; i < 4; i++) {
            const int idx = i * NTHREADS + tid;        // 0..2047
            // B: 256 rows x 8 chunks
            const int rB  = idx >> 3;
            const int chB = idx & 7;
            const uint32_t soB = (uint32_t)((rB * 128 + chB * 16) ^ ((rB & 7) << 4));
            const size_t  goB = (size_t)rB * 512 + k0 + chB * 8;
            cpasync16(sbase + 32768 + soB, Bh + goB);
            cpasync16(sbase + 65536 + soB, Bl + goB);
            // A: 128 rows x 8 chunks (first 1024 ids)
            if (i < 2) {
                const uint32_t soA = soB;
                cpasync16(sbase + soA,         Ah + goB);
                cpasync16(sbase + 16384 + soA, Al + goB);
            }
        }
        cp_commit();
    };

    float c[2][8][4];
#pragma unroll
    for (int mi = 0; mi < 2; mi++)
#pragma unroll
        for (int ni = 0; ni < 8; ni++)
#pragma unroll
            for (int j = 0; j < 4; j++) c[mi][ni][j] = 0.0f;

    load_stage(0, 0);
    load_stage(1, 1);

    const int grp = lane >> 3;
    const int sub = lane & 7;

#pragma unroll 1
    for (int cch = 0; cch < 8; cch++) {
        if (cch == 7) asm volatile("cp.async.wait_group 0;" ::: "memory");
        else          asm volatile("cp.async.wait_group 1;" ::: "memory");
        __syncthreads();

        const uint32_t sa = sb + (cch & 1) * STAGE_BYTES;

#pragma unroll
        for (int s = 0; s < 4; s++) {
            uint32_t aH[2][4], aL[2][4];
#pragma unroll
            for (int mi = 0; mi < 2; mi++) {
                const int rowA = wm * 32 + mi * 16 + (grp & 1) * 8 + sub;
                const int kbA  = s * 32 + (grp >> 1) * 16;
                const uint32_t off = (uint32_t)((rowA * 128 + kbA) ^ ((rowA & 7) << 4));
                ldsm4(sa + off,         aH[mi]);
                ldsm4(sa + 16384 + off, aL[mi]);
            }
#pragma unroll
            for (int p = 0; p < 4; p++) {
                uint32_t bH[4], bL[4];
                const int rowB = wn * 64 + (2 * p + (grp >> 1)) * 8 + sub;
                const int kbB  = s * 32 + (grp & 1) * 16;
                const uint32_t off = (uint32_t)((rowB * 128 + kbB) ^ ((rowB & 7) << 4));
                ldsm4(sa + 32768 + off, bH);
                ldsm4(sa + 65536 + off, bL);
#pragma unroll
                for (int mi = 0; mi < 2; mi++) {
                    mma16816(c[mi][2 * p + 0], aH[mi], &bH[0]);
                    mma16816(c[mi][2 * p + 1], aH[mi], &bH[2]);
                    mma16816(c[mi][2 * p + 0], aH[mi], &bL[0]);
                    mma16816(c[mi][2 * p + 1], aH[mi], &bL[2]);
                    mma16816(c[mi][2 * p + 0], aL[mi], &bH[0]);
                    mma16816(c[mi][2 * p + 1], aL[mi], &bH[2]);
                }
            }
        }
        __syncthreads();
        if (cch + 2 < 8) load_stage(cch & 1, cch + 2);
    }

    // epilogue: m=d rows, n=token cols -> g_u[b][d][l]
    const int q  = lane >> 2;
    const int t2 = (lane & 3) * 2;
    const int b  = n0 >> 11;
    const int lt = (n0 & 2047) + wn * 64;
#pragma unroll
    for (int mi = 0; mi < 2; mi++)
#pragma unroll
        for (int rr = 0; rr < 2; rr++) {
            const int d_row = m0 + wm * 32 + mi * 16 + rr * 8 + q;
            const float bi = __ldg(bias + d_row);
            float* dst = g_u + ((size_t)(b * DMODEL + d_row) << 11) + lt;
#pragma unroll
            for (int ni = 0; ni < 8; ni++) {
                float2 v;
                v.x = c[mi][ni][rr * 2 + 0] + bi;
                v.y = c[mi][ni][rr * 2 + 1] + bi;
                *(float2*)(dst + ni * 8 + t2) = v;
            }
        }
}

// ---------------------------------------------------------------------------
// GEMM2 (out_proj): out[token, n] = sum_k y[token,k] * W_out[n,k]
// A = y from K-major [b][d][l] fp16 hi/lo via ldmatrix.trans ([64k][128m] tile,
// 256B rows, chunk-XOR swizzle). B = W_out rows (256). Epilogue row-major out.
// ---------------------------------------------------------------------------
__global__ __launch_bounds__(NTHREADS, 1) void gemm_mma2(const __half* __restrict__ Wh,
                                                         const __half* __restrict__ Wl,
                                                         const float* __restrict__ bias,
                                                         float* __restrict__ Cout)
{
    extern __shared__ __align__(1024) char dyn[];
    const uint32_t sb = smem_u32(dyn);
    const int tid  = threadIdx.x;
    const int wid  = tid >> 5;
    const int lane = tid & 31;
    const int wm = wid & 3;
    const int wn = wid >> 2;
    const int n0 = blockIdx.x * 256;   // d_out
    const int m0 = blockIdx.y * 128;   // token
    const int b    = m0 >> 11;
    const int ltok = m0 & 2047;

    const __half* Bh = Wh + (size_t)n0 * 512;
    const __half* Bl = Wl + (size_t)n0 * 512;

    auto load_stage = [&](int stage, int c) {
        const int k0 = c * 64;
        const uint32_t sbase = sb + stage * STAGE_BYTES;
#pragma unroll
        for (int i = 0; i < 4; i++) {
            const int idx = i * NTHREADS + tid;        // 0..2047
            // B: 256 rows x 8 chunks
            const int rB  = idx >> 3;
            const int chB = idx & 7;
            const uint32_t soB = (uint32_t)((rB * 128 + chB * 16) ^ ((rB & 7) << 4));
            const size_t  goB = (size_t)rB * 512 + k0 + chB * 8;
            cpasync16(sbase + 32768 + soB, Bh + goB);
            cpasync16(sbase + 65536 + soB, Bl + goB);
            // A (y trans): 64 rows (k=d) x 16 chunks (m=token), 256B rows
            if (i < 2) {
                const int rA  = idx >> 4;
                const int chA = idx & 15;
                const uint32_t soA = (uint32_t)(rA * 256 + ((chA ^ (rA & 7)) << 4));
                const size_t  goA = ((size_t)(b * DMODEL + k0 + rA) << 11) + ltok + chA * 8;
                cpasync16(sbase + soA,         g_yh + goA);
                cpasync16(sbase + 16384 + soA, g_yl + goA);
            }
        }
        cp_commit();
    };

    float c[2][8][4];
#pragma unroll
    for (int mi = 0; mi < 2; mi++)
#pragma unroll
        for (int ni = 0; ni < 8; ni++)
#pragma unroll
            for (int j = 0; j < 4; j++) c[mi][ni][j] = 0.0f;

    load_stage(0, 0);
    load_stage(1, 1);

    const int grp = lane >> 3;
    const int sub = lane & 7;

#pragma unroll 1
    for (int cch = 0; cch < 8; cch++) {
        if (cch == 7) asm volatile("cp.async.wait_group 0;" ::: "memory");
        else          asm volatile("cp.async.wait_group 1;" ::: "memory");
        __syncthreads();

        const uint32_t sa = sb + (cch & 1) * STAGE_BYTES;

#pragma unroll
        for (int s = 0; s < 4; s++) {
            uint32_t aH[2][4], aL[2][4];
#pragma unroll
            for (int mi = 0; mi < 2; mi++) {
                const int krow = s * 16 + (grp >> 1) * 8 + sub;
                const int mcol = wm * 32 + mi * 16 + (grp & 1) * 8;
                const int chunk = mcol >> 3;
                const uint32_t off = (uint32_t)(krow * 256 + ((chunk ^ (krow & 7)) << 4));
                ldsm4t(sa + off,         aH[mi]);
                ldsm4t(sa + 16384 + off, aL[mi]);
            }
#pragma unroll
            for (int p = 0; p < 4; p++) {
                uint32_t bH[4], bL[4];
                const int rowB = wn * 64 + (2 * p + (grp >> 1)) * 8 + sub;
                const int kbB  = s * 32 + (grp & 1) * 16;
                const uint32_t off = (uint32_t)((rowB * 128 + kbB) ^ ((rowB & 7) << 4));
                ldsm4(sa + 32768 + off, bH);
                ldsm4(sa + 65536 + off, bL);
#pragma unroll
                for (int mi = 0; mi < 2; mi++) {
                    mma16816(c[mi][2 * p + 0], aH[mi], &bH[0]);
                    mma16816(c[mi][2 * p + 1], aH[mi], &bH[2]);
                    mma16816(c[mi][2 * p + 0], aH[mi], &bL[0]);
                    mma16816(c[mi][2 * p + 1], aH[mi], &bL[2]);
                    mma16816(c[mi][2 * p + 0], aL[mi], &bH[0]);
                    mma16816(c[mi][2 * p + 1], aL[mi], &bH[2]);
                }
            }
        }
        __syncthreads();
        if (cch + 2 < 8) load_stage(cch & 1, cch + 2);
    }

    // epilogue: row-major out
    const int q  = lane >> 2;
    const int t2 = (lane & 3) * 2;
#pragma unroll
    for (int mi = 0; mi < 2; mi++)
#pragma unroll
        for (int rr = 0; rr < 2; rr++) {
            const int row = m0 + wm * 32 + mi * 16 + rr * 8 + q;
            float* dst = Cout + (size_t)row * 512 + n0 + wn * 64;
#pragma unroll
            for (int ni = 0; ni < 8; ni++) {
                const float2 bv = *(const float2*)(bias + n0 + wn * 64 + ni * 8 + t2);
                float2 v;
                v.x = c[mi][ni][rr * 2 + 0] + bv.x;
                v.y = c[mi][ni][rr * 2 + 1] + bv.y;
                *(float2*)(dst + ni * 8 + t2) = v;
            }
        }
}

// ---------------------------------------------------------------------------
// SSM recurrence scan: one warp per (b,d); 2 states/lane.
// Writes y as fp16 hi/lo in [b][d][l] (consumed by gemm_mma2 via trans).
// ---------------------------------------------------------------------------
__global__ __launch_bounds__(256) void s4_scan(const float* __restrict__ A_log,
                                               const float* __restrict__ Bp,
                                               const float* __restrict__ Cp,
                                               const float* __restrict__ Dp,
                                               const float* __restrict__ dt)
{
    const int warp = (blockIdx.x * blockDim.x + threadIdx.x) >> 5;
    const int lane = threadIdx.x & 31;
    const int d = warp & (DMODEL - 1);
    const int b = warp >> 9;

    const float dtd = dt[d];
    const int i0 = d * DSTATE + lane;
    const int i1 = i0 + 32;

    const float r0 = expf(-expf(A_log[i0]) * dtd);
    const float r1 = expf(-expf(A_log[i1]) * dtd);
    const float c0 = Cp[i0] * Bp[i0] * dtd;
    const float c1 = Cp[i1] * Bp[i1] * dtd;
    const float Dd = Dp[d];

    const size_t rowoff = (size_t)(b * DMODEL + d) << 11;
    const float* ub = g_u + rowoff;
    __half* yh = g_yh + rowoff;
    __half* yl = g_yl + rowoff;

    float z0 = 0.0f, z1 = 0.0f;

    for (int t0 = 0; t0 < SEQLEN; t0 += 32) {
        const float uv = ub[t0 + lane];
        float p[32];
#pragma unroll
        for (int i = 0; i < 32; i++) {
            const float uu = __shfl_sync(0xffffffffu, uv, i);
            z0 = fmaf(r0, z0, uu);
            z1 = fmaf(r1, z1, uu);
            p[i] = fmaf(c0, z0, c1 * z1);
        }
        const bool h16 = (lane & 16);
        float s16[16];
#pragma unroll
        for (int k = 0; k < 16; k++) {
            const float keep = h16 ? p[k + 16] : p[k];
            const float send = h16 ? p[k] : p[k + 16];
            s16[k] = keep + __shfl_xor_sync(0xffffffffu, send, 16);
        }
        const bool h8 = (lane & 8);
        float s8[8];
#pragma unroll
        for (int k = 0; k < 8; k++) {
            const float keep = h8 ? s16[k + 8] : s16[k];
            const float send = h8 ? s16[k] : s16[k + 8];
            s8[k] = keep + __shfl_xor_sync(0xffffffffu, send, 8);
        }
        const bool h4 = (lane & 4);
        float s4[4];
#pragma unroll
        for (int k = 0; k < 4; k++) {
            const float keep = h4 ? s8[k + 4] : s8[k];
            const float send = h4 ? s8[k] : s8[k + 4];
            s4[k] = keep + __shfl_xor_sync(0xffffffffu, send, 4);
        }
        const bool h2 = (lane & 2);
        float s2[2];
#pragma unroll
        for (int k = 0; k < 2; k++) {
            const float keep = h2 ? s4[k + 2] : s4[k];
            const float send = h2 ? s4[k] : s4[k + 2];
            s2[k] = keep + __shfl_xor_sync(0xffffffffu, send, 2);
        }
        const bool h1 = (lane & 1);
        const float keep = h1 ? s2[1] : s2[0];
        const float send = h1 ? s2[0] : s2[1];
        const float tot = keep + __shfl_xor_sync(0xffffffffu, send, 1);

        const float yv = fmaf(Dd, uv, tot);
        const __half hv = __float2half_rn(yv);
        yh[t0 + lane] = hv;
        yl[t0 + lane] = __float2half_rn(yv - __half2float(hv));
    }
}

// ---------------------------------------------------------------------------
extern "C" void kernel_launch(void* const* d_in, const int* in_sizes, int n_in,
                              void* d_out, int out_size)
{
    const float* x     = (const float*)d_in[0];
    const float* W_in  = (const float*)d_in[1];
    const float* b_in  = (const float*)d_in[2];
    const float* A_log = (const float*)d_in[3];
    const float* B     = (const float*)d_in[4];
    const float* C     = (const float*)d_in[5];
    const float* D     = (const float*)d_in[6];
    const float* dt    = (const float*)d_in[7];
    const float* W_out = (const float*)d_in[8];
    const float* b_out = (const float*)d_in[9];
    float* out = (float*)d_out;

    static bool attr_done = false;
    if (!attr_done) {
        cudaFuncSetAttribute(gemm_mma1, cudaFuncAttributeMaxDynamicSharedMemorySize, SMEM_BYTES);
        cudaFuncSetAttribute(gemm_mma2, cudaFuncAttributeMaxDynamicSharedMemorySize, SMEM_BYTES);
        attr_done = true;
    }

    __half *p_ah, *p_al, *p_wh, *p_wl;
    cudaGetSymbolAddress((void**)&p_ah, g_ah);
    cudaGetSymbolAddress((void**)&p_al, g_al);
    cudaGetSymbolAddress((void**)&p_wh, g_wh);
    cudaGetSymbolAddress((void**)&p_wl, g_wl);

    // 1) split-convert x + W_in + W_out (single launch)
    {
        const int total = N4_X + 2 * N4_W;
        convert_all<<<(total + 255) / 256, 256>>>(x, W_in, W_out, p_ah, p_al, p_wh, p_wl);
    }

    // 2) in_proj: D[d, token] -> g_u[b][d][l]   (grid 32x4 = 128 CTAs, 1 wave)
    {
        dim3 g(MTOT / 256, DMODEL / 128);
        gemm_mma1<<<g, NTHREADS, SMEM_BYTES>>>(p_wh, p_wl, p_ah, p_al, b_in);
    }

    // 3) SSM recurrence: g_u -> g_yh/g_yl  [b][d][l] fp16 hi/lo
    s4_scan<<<(BATCH * DMODEL) / 8, 256>>>(A_log, B, C, D, dt);

    // 4) out_proj: y (trans) @ W_out^T -> out   (grid 2x64 = 128 CTAs, 1 wave)
    {
        dim3 g(DMODEL / 256, MTOT / 128);
        gemm_mma2<<<g, NTHREADS, SMEM_BYTES>>>(p_wh + DMODEL * DMODEL,
                                               p_wl + DMODEL * DMODEL, b_out, out);
    }
}

// round 9
// speedup vs baseline: 1.2094x; 1.1465x over previous
#include <cuda_runtime.h>
#include <cuda_fp16.h>
#include <math.h>
#include <stdint.h>

// Problem constants
#define BATCH   4
#define SEQLEN  2048
#define DMODEL  512
#define DSTATE  64
#define MTOT    (BATCH * SEQLEN)   // 8192

// ---------------------------------------------------------------------------
// Device scratch (no cudaMalloc allowed)
// ---------------------------------------------------------------------------
__device__ float  g_u[BATCH * DMODEL * SEQLEN];   // [b][d][l] fp32 (scan input)
__device__ __half g_yh[BATCH * DMODEL * SEQLEN];  // [b][d][l] y hi
__device__ __half g_yl[BATCH * DMODEL * SEQLEN];  // [b][d][l] y lo
__device__ __half g_ah[MTOT * DMODEL];            // x hi [token][k]
__device__ __half g_al[MTOT * DMODEL];            // x lo [token][k]
__device__ __half g_wh[2 * DMODEL * DMODEL];      // W_in | W_out hi (lo dropped)

// ---------------------------------------------------------------------------
// PTX helpers
// ---------------------------------------------------------------------------
__device__ __forceinline__ uint32_t smem_u32(const void* p) {
    uint32_t a;
    asm("{ .reg .u64 t; cvta.to.shared.u64 t, %1; cvt.u32.u64 %0, t; }" : "=r"(a) : "l"(p));
    return a;
}
__device__ __forceinline__ void cpasync16(uint32_t s, const void* g) {
    asm volatile("cp.async.cg.shared.global [%0], [%1], 16;" :: "r"(s), "l"(g));
}
__device__ __forceinline__ void cp_commit() {
    asm volatile("cp.async.commit_group;" ::: "memory");
}
__device__ __forceinline__ void ldsm4(uint32_t a, uint32_t* r) {
    asm volatile("ldmatrix.sync.aligned.m8n8.x4.shared.b16 {%0,%1,%2,%3}, [%4];"
                 : "=r"(r[0]), "=r"(r[1]), "=r"(r[2]), "=r"(r[3]) : "r"(a));
}
__device__ __forceinline__ void ldsm4t(uint32_t a, uint32_t* r) {
    asm volatile("ldmatrix.sync.aligned.m8n8.x4.trans.shared.b16 {%0,%1,%2,%3}, [%4];"
                 : "=r"(r[0]), "=r"(r[1]), "=r"(r[2]), "=r"(r[3]) : "r"(a));
}
__device__ __forceinline__ void mma16816(float* c, const uint32_t* a, const uint32_t* b) {
    asm volatile(
        "mma.sync.aligned.m16n8k16.row.col.f32.f16.f16.f32 "
        "{%0,%1,%2,%3}, {%4,%5,%6,%7}, {%8,%9}, {%0,%1,%2,%3};"
        : "+f"(c[0]), "+f"(c[1]), "+f"(c[2]), "+f"(c[3])
        : "r"(a[0]), "r"(a[1]), "r"(a[2]), "r"(a[3]), "r"(b[0]), "r"(b[1]));
}

// ---------------------------------------------------------------------------
// Conversion: x -> fp16 hi/lo split; weights -> fp16 hi only (lo dropped:
// 2-pass split scheme, error ~2^-12 relative, well under 1e-3 threshold).
// ---------------------------------------------------------------------------
#define N4_X (MTOT * DMODEL / 4)
#define N4_W (DMODEL * DMODEL / 4)

__global__ __launch_bounds__(256) void convert_all(const float* __restrict__ x,
                                                   const float* __restrict__ w_in,
                                                   const float* __restrict__ w_out,
                                                   __half* __restrict__ ah,
                                                   __half* __restrict__ al,
                                                   __half* __restrict__ wh)
{
    int i = blockIdx.x * 256 + threadIdx.x;
    if (i < N4_X) {
        float4 v = ((const float4*)x)[i];
        __half h0 = __float2half_rn(v.x);
        __half h1 = __float2half_rn(v.y);
        __half h2 = __float2half_rn(v.z);
        __half h3 = __float2half_rn(v.w);
        __half l0 = __float2half_rn(v.x - __half2float(h0));
        __half l1 = __float2half_rn(v.y - __half2float(h1));
        __half l2 = __float2half_rn(v.z - __half2float(h2));
        __half l3 = __float2half_rn(v.w - __half2float(h3));
        uint2 ph, pl;
        ph.x = (uint32_t)__half_as_ushort(h0) | ((uint32_t)__half_as_ushort(h1) << 16);
        ph.y = (uint32_t)__half_as_ushort(h2) | ((uint32_t)__half_as_ushort(h3) << 16);
        pl.x = (uint32_t)__half_as_ushort(l0) | ((uint32_t)__half_as_ushort(l1) << 16);
        pl.y = (uint32_t)__half_as_ushort(l2) | ((uint32_t)__half_as_ushort(l3) << 16);
        ((uint2*)ah)[i] = ph;
        ((uint2*)al)[i] = pl;
    } else if (i < N4_X + 2 * N4_W) {
        const int off = i - N4_X;
        const float4 v = (off < N4_W) ? ((const float4*)w_in)[off]
                                      : ((const float4*)w_out)[off - N4_W];
        uint2 ph;
        ph.x = (uint32_t)__half_as_ushort(__float2half_rn(v.x)) |
               ((uint32_t)__half_as_ushort(__float2half_rn(v.y)) << 16);
        ph.y = (uint32_t)__half_as_ushort(__float2half_rn(v.z)) |
               ((uint32_t)__half_as_ushort(__float2half_rn(v.w)) << 16);
        ((uint2*)wh)[off] = ph;
    }
}

// ---------------------------------------------------------------------------
// GEMM config: CTA tile 128(M) x 256(N), K-chunk 64, 2 stages, 16 warps 4x4,
// warp tile 32x64. Single wave: grid = 128 CTAs. 2-pass split-fp16.
// ---------------------------------------------------------------------------
#define NTHREADS 512

// GEMM1 stage: Wh(A) 16KB @0, xh(B) 32KB @16384, xl(B) 32KB @49152 -> 80KB
#define STAGE1_BYTES 81920
#define SMEM1_BYTES  (2 * STAGE1_BYTES)   // 160 KB
// GEMM2 stage: yh(A) 16KB @0, yl(A) 16KB @16384, Wh(B) 32KB @32768 -> 64KB
#define STAGE2_BYTES 65536
#define SMEM2_BYTES  (2 * STAGE2_BYTES)   // 128 KB

// ---------------------------------------------------------------------------
// GEMM1 (in_proj): D[d, token] = sum_k Wh[d,k] * (xh+xl)[token,k]
// Epilogue -> g_u[b][d][l].
// ---------------------------------------------------------------------------
__global__ __launch_bounds__(NTHREADS, 1) void gemm_mma1(const __half* __restrict__ Wh,
                                                         const __half* __restrict__ Xh,
                                                         const __half* __restrict__ Xl,
                                                         const float* __restrict__ bias)
{
    extern __shared__ __align__(1024) char dyn[];
    const uint32_t sb = smem_u32(dyn);
    const int tid  = threadIdx.x;
    const int wid  = tid >> 5;
    const int lane = tid & 31;
    const int wm = wid & 3;          // 4 M-groups of 32 rows
    const int wn = wid >> 2;         // 4 N-groups of 64 cols
    const int n0 = blockIdx.x * 256; // token
    const int m0 = blockIdx.y * 128; // d

    const __half* Ah = Wh + (size_t)m0 * 512;
    const __half* Bh = Xh + (size_t)n0 * 512;
    const __half* Bl = Xl + (size_t)n0 * 512;

    auto load_stage = [&](int stage, int c) {
        const int k0 = c * 64;
        const uint32_t sbase = sb + stage * STAGE1_BYTES;
#pragma unroll
        for (int i = 0; i < 4; i++) {
            const int idx = i * NTHREADS + tid;        // 0..2047
            const int rB  = idx >> 3;                  // 0..255
            const int chB = idx & 7;
            const uint32_t soB = (uint32_t)((rB * 128 + chB * 16) ^ ((rB & 7) << 4));
            const size_t  goB = (size_t)rB * 512 + k0 + chB * 8;
            cpasync16(sbase + 16384 + soB, Bh + goB);
            cpasync16(sbase + 49152 + soB, Bl + goB);
            if (i < 2) {                               // A: 128 rows
                cpasync16(sbase + soB, Ah + goB);
            }
        }
        cp_commit();
    };

    float c[2][8][4];
#pragma unroll
    for (int mi = 0; mi < 2; mi++)
#pragma unroll
        for (int ni = 0; ni < 8; ni++)
#pragma unroll
            for (int j = 0; j < 4; j++) c[mi][ni][j] = 0.0f;

    load_stage(0, 0);
    load_stage(1, 1);

    const int grp = lane >> 3;
    const int sub = lane & 7;

#pragma unroll 1
    for (int cch = 0; cch < 8; cch++) {
        if (cch == 7) asm volatile("cp.async.wait_group 0;" ::: "memory");
        else          asm volatile("cp.async.wait_group 1;" ::: "memory");
        __syncthreads();

        const uint32_t sa = sb + (cch & 1) * STAGE1_BYTES;

#pragma unroll
        for (int s = 0; s < 4; s++) {
            uint32_t aH[2][4];
#pragma unroll
            for (int mi = 0; mi < 2; mi++) {
                const int rowA = wm * 32 + mi * 16 + (grp & 1) * 8 + sub;
                const int kbA  = s * 32 + (grp >> 1) * 16;
                const uint32_t off = (uint32_t)((rowA * 128 + kbA) ^ ((rowA & 7) << 4));
                ldsm4(sa + off, aH[mi]);
            }
#pragma unroll
            for (int p = 0; p < 4; p++) {
                uint32_t bH[4], bL[4];
                const int rowB = wn * 64 + (2 * p + (grp >> 1)) * 8 + sub;
                const int kbB  = s * 32 + (grp & 1) * 16;
                const uint32_t off = (uint32_t)((rowB * 128 + kbB) ^ ((rowB & 7) << 4));
                ldsm4(sa + 16384 + off, bH);
                ldsm4(sa + 49152 + off, bL);
#pragma unroll
                for (int mi = 0; mi < 2; mi++) {
                    mma16816(c[mi][2 * p + 0], aH[mi], &bH[0]);
                    mma16816(c[mi][2 * p + 1], aH[mi], &bH[2]);
                    mma16816(c[mi][2 * p + 0], aH[mi], &bL[0]);
                    mma16816(c[mi][2 * p + 1], aH[mi], &bL[2]);
                }
            }
        }
        __syncthreads();
        if (cch + 2 < 8) load_stage(cch & 1, cch + 2);
    }

    // epilogue: m=d rows, n=token cols -> g_u[b][d][l]
    const int q  = lane >> 2;
    const int t2 = (lane & 3) * 2;
    const int b  = n0 >> 11;
    const int lt = (n0 & 2047) + wn * 64;
#pragma unroll
    for (int mi = 0; mi < 2; mi++)
#pragma unroll
        for (int rr = 0; rr < 2; rr++) {
            const int d_row = m0 + wm * 32 + mi * 16 + rr * 8 + q;
            const float bi = __ldg(bias + d_row);
            float* dst = g_u + ((size_t)(b * DMODEL + d_row) << 11) + lt;
#pragma unroll
            for (int ni = 0; ni < 8; ni++) {
                float2 v;
                v.x = c[mi][ni][rr * 2 + 0] + bi;
                v.y = c[mi][ni][rr * 2 + 1] + bi;
                *(float2*)(dst + ni * 8 + t2) = v;
            }
        }
}

// ---------------------------------------------------------------------------
// GEMM2 (out_proj): out[token, n] = sum_k (yh+yl)[token,k] * Wh[n,k]
// A = y from K-major [b][d][l] fp16 hi/lo via ldmatrix.trans.
// ---------------------------------------------------------------------------
__global__ __launch_bounds__(NTHREADS, 1) void gemm_mma2(const __half* __restrict__ Wh,
                                                         const float* __restrict__ bias,
                                                         float* __restrict__ Cout)
{
    extern __shared__ __align__(1024) char dyn[];
    const uint32_t sb = smem_u32(dyn);
    const int tid  = threadIdx.x;
    const int wid  = tid >> 5;
    const int lane = tid & 31;
    const int wm = wid & 3;
    const int wn = wid >> 2;
    const int n0 = blockIdx.x * 256;   // d_out
    const int m0 = blockIdx.y * 128;   // token
    const int b    = m0 >> 11;
    const int ltok = m0 & 2047;

    const __half* Bh = Wh + (size_t)n0 * 512;

    auto load_stage = [&](int stage, int c) {
        const int k0 = c * 64;
        const uint32_t sbase = sb + stage * STAGE2_BYTES;
#pragma unroll
        for (int i = 0; i < 4; i++) {
            const int idx = i * NTHREADS + tid;        // 0..2047
            // B: 256 rows x 8 chunks
            const int rB  = idx >> 3;
            const int chB = idx & 7;
            const uint32_t soB = (uint32_t)((rB * 128 + chB * 16) ^ ((rB & 7) << 4));
            const size_t  goB = (size_t)rB * 512 + k0 + chB * 8;
            cpasync16(sbase + 32768 + soB, Bh + goB);
            // A (y trans): 64 rows (k=d) x 16 chunks (m=token), 256B rows
            if (i < 2) {
                const int rA  = idx >> 4;
                const int chA = idx & 15;
                const uint32_t soA = (uint32_t)(rA * 256 + ((chA ^ (rA & 7)) << 4));
                const size_t  goA = ((size_t)(b * DMODEL + k0 + rA) << 11) + ltok + chA * 8;
                cpasync16(sbase + soA,         g_yh + goA);
                cpasync16(sbase + 16384 + soA, g_yl + goA);
            }
        }
        cp_commit();
    };

    float c[2][8][4];
#pragma unroll
    for (int mi = 0; mi < 2; mi++)
#pragma unroll
        for (int ni = 0; ni < 8; ni++)
#pragma unroll
            for (int j = 0; j < 4; j++) c[mi][ni][j] = 0.0f;

    load_stage(0, 0);
    load_stage(1, 1);

    const int grp = lane >> 3;
    const int sub = lane & 7;

#pragma unroll 1
    for (int cch = 0; cch < 8; cch++) {
        if (cch == 7) asm volatile("cp.async.wait_group 0;" ::: "memory");
        else          asm volatile("cp.async.wait_group 1;" ::: "memory");
        __syncthreads();

        const uint32_t sa = sb + (cch & 1) * STAGE2_BYTES;

#pragma unroll
        for (int s = 0; s < 4; s++) {
            uint32_t aH[2][4], aL[2][4];
#pragma unroll
            for (int mi = 0; mi < 2; mi++) {
                const int krow = s * 16 + (grp >> 1) * 8 + sub;
                const int mcol = wm * 32 + mi * 16 + (grp & 1) * 8;
                const int chunk = mcol >> 3;
                const uint32_t off = (uint32_t)(krow * 256 + ((chunk ^ (krow & 7)) << 4));
                ldsm4t(sa + off,         aH[mi]);
                ldsm4t(sa + 16384 + off, aL[mi]);
            }
#pragma unroll
            for (int p = 0; p < 4; p++) {
                uint32_t bH[4];
                const int rowB = wn * 64 + (2 * p + (grp >> 1)) * 8 + sub;
                const int kbB  = s * 32 + (grp & 1) * 16;
                const uint32_t off = (uint32_t)((rowB * 128 + kbB) ^ ((rowB & 7) << 4));
                ldsm4(sa + 32768 + off, bH);
#pragma unroll
                for (int mi = 0; mi < 2; mi++) {
                    mma16816(c[mi][2 * p + 0], aH[mi], &bH[0]);
                    mma16816(c[mi][2 * p + 1], aH[mi], &bH[2]);
                    mma16816(c[mi][2 * p + 0], aL[mi], &bH[0]);
                    mma16816(c[mi][2 * p + 1], aL[mi], &bH[2]);
                }
            }
        }
        __syncthreads();
        if (cch + 2 < 8) load_stage(cch & 1, cch + 2);
    }

    // epilogue: row-major out
    const int q  = lane >> 2;
    const int t2 = (lane & 3) * 2;
#pragma unroll
    for (int mi = 0; mi < 2; mi++)
#pragma unroll
        for (int rr = 0; rr < 2; rr++) {
            const int row = m0 + wm * 32 + mi * 16 + rr * 8 + q;
            float* dst = Cout + (size_t)row * 512 + n0 + wn * 64;
#pragma unroll
            for (int ni = 0; ni < 8; ni++) {
                const float2 bv = *(const float2*)(bias + n0 + wn * 64 + ni * 8 + t2);
                float2 v;
                v.x = c[mi][ni][rr * 2 + 0] + bv.x;
                v.y = c[mi][ni][rr * 2 + 1] + bv.y;
                *(float2*)(dst + ni * 8 + t2) = v;
            }
        }
}

// ---------------------------------------------------------------------------
// SSM recurrence scan: one warp per (b,d); 2 states/lane.
// Writes y as fp16 hi/lo in [b][d][l] (consumed by gemm_mma2 via trans).
// ---------------------------------------------------------------------------
__global__ __launch_bounds__(256) void s4_scan(const float* __restrict__ A_log,
                                               const float* __restrict__ Bp,
                                               const float* __restrict__ Cp,
                                               const float* __restrict__ Dp,
                                               const float* __restrict__ dt)
{
    const int warp = (blockIdx.x * blockDim.x + threadIdx.x) >> 5;
    const int lane = threadIdx.x & 31;
    const int d = warp & (DMODEL - 1);
    const int b = warp >> 9;

    const float dtd = dt[d];
    const int i0 = d * DSTATE + lane;
    const int i1 = i0 + 32;

    const float r0 = expf(-expf(A_log[i0]) * dtd);
    const float r1 = expf(-expf(A_log[i1]) * dtd);
    const float c0 = Cp[i0] * Bp[i0] * dtd;
    const float c1 = Cp[i1] * Bp[i1] * dtd;
    const float Dd = Dp[d];

    const size_t rowoff = (size_t)(b * DMODEL + d) << 11;
    const float* ub = g_u + rowoff;
    __half* yh = g_yh + rowoff;
    __half* yl = g_yl + rowoff;

    float z0 = 0.0f, z1 = 0.0f;

    for (int t0 = 0; t0 < SEQLEN; t0 += 32) {
        const float uv = ub[t0 + lane];
        float p[32];
#pragma unroll
        for (int i = 0; i < 32; i++) {
            const float uu = __shfl_sync(0xffffffffu, uv, i);
            z0 = fmaf(r0, z0, uu);
            z1 = fmaf(r1, z1, uu);
            p[i] = fmaf(c0, z0, c1 * z1);
        }
        const bool h16 = (lane & 16);
        float s16[16];
#pragma unroll
        for (int k = 0; k < 16; k++) {
            const float keep = h16 ? p[k + 16] : p[k];
            const float send = h16 ? p[k] : p[k + 16];
            s16[k] = keep + __shfl_xor_sync(0xffffffffu, send, 16);
        }
        const bool h8 = (lane & 8);
        float s8[8];
#pragma unroll
        for (int k = 0; k < 8; k++) {
            const float keep = h8 ? s16[k + 8] : s16[k];
            const float send = h8 ? s16[k] : s16[k + 8];
            s8[k] = keep + __shfl_xor_sync(0xffffffffu, send, 8);
        }
        const bool h4 = (lane & 4);
        float s4[4];
#pragma unroll
        for (int k = 0; k < 4; k++) {
            const float keep = h4 ? s8[k + 4] : s8[k];
            const float send = h4 ? s8[k] : s8[k + 4];
            s4[k] = keep + __shfl_xor_sync(0xffffffffu, send, 4);
        }
        const bool h2 = (lane & 2);
        float s2[2];
#pragma unroll
        for (int k = 0; k < 2; k++) {
            const float keep = h2 ? s4[k + 2] : s4[k];
            const float send = h2 ? s4[k] : s4[k + 2];
            s2[k] = keep + __shfl_xor_sync(0xffffffffu, send, 2);
        }
        const bool h1 = (lane & 1);
        const float keep = h1 ? s2[1] : s2[0];
        const float send = h1 ? s2[0] : s2[1];
        const float tot = keep + __shfl_xor_sync(0xffffffffu, send, 1);

        const float yv = fmaf(Dd, uv, tot);
        const __half hv = __float2half_rn(yv);
        yh[t0 + lane] = hv;
        yl[t0 + lane] = __float2half_rn(yv - __half2float(hv));
    }
}

// ---------------------------------------------------------------------------
extern "C" void kernel_launch(void* const* d_in, const int* in_sizes, int n_in,
                              void* d_out, int out_size)
{
    const float* x     = (const float*)d_in[0];
    const float* W_in  = (const float*)d_in[1];
    const float* b_in  = (const float*)d_in[2];
    const float* A_log = (const float*)d_in[3];
    const float* B     = (const float*)d_in[4];
    const float* C     = (const float*)d_in[5];
    const float* D     = (const float*)d_in[6];
    const float* dt    = (const float*)d_in[7];
    const float* W_out = (const float*)d_in[8];
    const float* b_out = (const float*)d_in[9];
    float* out = (float*)d_out;

    static bool attr_done = false;
    if (!attr_done) {
        cudaFuncSetAttribute(gemm_mma1, cudaFuncAttributeMaxDynamicSharedMemorySize, SMEM1_BYTES);
        cudaFuncSetAttribute(gemm_mma2, cudaFuncAttributeMaxDynamicSharedMemorySize, SMEM2_BYTES);
        attr_done = true;
    }

    __half *p_ah, *p_al, *p_wh;
    cudaGetSymbolAddress((void**)&p_ah, g_ah);
    cudaGetSymbolAddress((void**)&p_al, g_al);
    cudaGetSymbolAddress((void**)&p_wh, g_wh);

    // 1) convert: x -> hi/lo, weights -> hi only (single launch)
    {
        const int total = N4_X + 2 * N4_W;
        convert_all<<<(total + 255) / 256, 256>>>(x, W_in, W_out, p_ah, p_al, p_wh);
    }

    // 2) in_proj: D[d, token] -> g_u[b][d][l]   (grid 32x4 = 128 CTAs, 1 wave)
    {
        dim3 g(MTOT / 256, DMODEL / 128);
        gemm_mma1<<<g, NTHREADS, SMEM1_BYTES>>>(p_wh, p_ah, p_al, b_in);
    }

    // 3) SSM recurrence: g_u -> g_yh/g_yl  [b][d][l] fp16 hi/lo
    s4_scan<<<(BATCH * DMODEL) / 8, 256>>>(A_log, B, C, D, dt);

    // 4) out_proj: y (trans) @ W_out_h^T -> out  (grid 2x64 = 128 CTAs, 1 wave)
    {
        dim3 g(DMODEL / 256, MTOT / 128);
        gemm_mma2<<<g, NTHREADS, SMEM2_BYTES>>>(p_wh + DMODEL * DMODEL, b_out, out);
    }
}

// round 10
// speedup vs baseline: 1.3513x; 1.1174x over previous
#include <cuda_runtime.h>
#include <cuda_fp16.h>
#include <math.h>
#include <stdint.h>

// Problem constants
#define BATCH   4
#define SEQLEN  2048
#define DMODEL  512
#define DSTATE  64
#define MTOT    (BATCH * SEQLEN)   // 8192

// ---------------------------------------------------------------------------
// Device scratch (no cudaMalloc allowed)
// ---------------------------------------------------------------------------
__device__ float  g_u[BATCH * DMODEL * SEQLEN];   // [b][d][l] fp32 (scan input)
__device__ __half g_yh[BATCH * DMODEL * SEQLEN];  // [b][d][l] y hi (only)
__device__ __half g_ah[MTOT * DMODEL];            // x hi [token][k]
__device__ __half g_al[MTOT * DMODEL];            // x lo [token][k]
__device__ __half g_wh[2 * DMODEL * DMODEL];      // W_in | W_out hi

// ---------------------------------------------------------------------------
// PTX helpers
// ---------------------------------------------------------------------------
__device__ __forceinline__ uint32_t smem_u32(const void* p) {
    uint32_t a;
    asm("{ .reg .u64 t; cvta.to.shared.u64 t, %1; cvt.u32.u64 %0, t; }" : "=r"(a) : "l"(p));
    return a;
}
__device__ __forceinline__ void cpasync16(uint32_t s, const void* g) {
    asm volatile("cp.async.cg.shared.global [%0], [%1], 16;" :: "r"(s), "l"(g));
}
__device__ __forceinline__ void cp_commit() {
    asm volatile("cp.async.commit_group;" ::: "memory");
}
__device__ __forceinline__ void ldsm4(uint32_t a, uint32_t* r) {
    asm volatile("ldmatrix.sync.aligned.m8n8.x4.shared.b16 {%0,%1,%2,%3}, [%4];"
                 : "=r"(r[0]), "=r"(r[1]), "=r"(r[2]), "=r"(r[3]) : "r"(a));
}
__device__ __forceinline__ void ldsm4t(uint32_t a, uint32_t* r) {
    asm volatile("ldmatrix.sync.aligned.m8n8.x4.trans.shared.b16 {%0,%1,%2,%3}, [%4];"
                 : "=r"(r[0]), "=r"(r[1]), "=r"(r[2]), "=r"(r[3]) : "r"(a));
}
__device__ __forceinline__ void mma16816(float* c, const uint32_t* a, const uint32_t* b) {
    asm volatile(
        "mma.sync.aligned.m16n8k16.row.col.f32.f16.f16.f32 "
        "{%0,%1,%2,%3}, {%4,%5,%6,%7}, {%8,%9}, {%0,%1,%2,%3};"
        : "+f"(c[0]), "+f"(c[1]), "+f"(c[2]), "+f"(c[3])
        : "r"(a[0]), "r"(a[1]), "r"(a[2]), "r"(a[3]), "r"(b[0]), "r"(b[1]));
}

// ---------------------------------------------------------------------------
// Conversion: x -> fp16 hi/lo split; weights -> fp16 hi only.
// ---------------------------------------------------------------------------
#define N4_X (MTOT * DMODEL / 4)
#define N4_W (DMODEL * DMODEL / 4)

__global__ __launch_bounds__(256) void convert_all(const float* __restrict__ x,
                                                   const float* __restrict__ w_in,
                                                   const float* __restrict__ w_out,
                                                   __half* __restrict__ ah,
                                                   __half* __restrict__ al,
                                                   __half* __restrict__ wh)
{
    int i = blockIdx.x * 256 + threadIdx.x;
    if (i < N4_X) {
        float4 v = ((const float4*)x)[i];
        __half h0 = __float2half_rn(v.x);
        __half h1 = __float2half_rn(v.y);
        __half h2 = __float2half_rn(v.z);
        __half h3 = __float2half_rn(v.w);
        __half l0 = __float2half_rn(v.x - __half2float(h0));
        __half l1 = __float2half_rn(v.y - __half2float(h1));
        __half l2 = __float2half_rn(v.z - __half2float(h2));
        __half l3 = __float2half_rn(v.w - __half2float(h3));
        uint2 ph, pl;
        ph.x = (uint32_t)__half_as_ushort(h0) | ((uint32_t)__half_as_ushort(h1) << 16);
        ph.y = (uint32_t)__half_as_ushort(h2) | ((uint32_t)__half_as_ushort(h3) << 16);
        pl.x = (uint32_t)__half_as_ushort(l0) | ((uint32_t)__half_as_ushort(l1) << 16);
        pl.y = (uint32_t)__half_as_ushort(l2) | ((uint32_t)__half_as_ushort(l3) << 16);
        ((uint2*)ah)[i] = ph;
        ((uint2*)al)[i] = pl;
    } else if (i < N4_X + 2 * N4_W) {
        const int off = i - N4_X;
        const float4 v = (off < N4_W) ? ((const float4*)w_in)[off]
                                      : ((const float4*)w_out)[off - N4_W];
        uint2 ph;
        ph.x = (uint32_t)__half_as_ushort(__float2half_rn(v.x)) |
               ((uint32_t)__half_as_ushort(__float2half_rn(v.y)) << 16);
        ph.y = (uint32_t)__half_as_ushort(__float2half_rn(v.z)) |
               ((uint32_t)__half_as_ushort(__float2half_rn(v.w)) << 16);
        ((uint2*)wh)[off] = ph;
    }
}

// ---------------------------------------------------------------------------
// GEMM config: CTA tile 128(M) x 256(N), K-chunk 64, 2 stages, 16 warps 4x4,
// warp tile 32x64. Single wave: grid = 128 CTAs.
// ---------------------------------------------------------------------------
#define NTHREADS 512

// GEMM1 stage: Wh(A) 16KB @0, xh(B) 32KB @16384, xl(B) 32KB @49152 -> 80KB
#define STAGE1_BYTES 81920
#define SMEM1_BYTES  (2 * STAGE1_BYTES)   // 160 KB
// GEMM2 stage: yh(A) 16KB @0, Wh(B) 32KB @16384 -> 48KB
#define STAGE2_BYTES 49152
#define SMEM2_BYTES  (2 * STAGE2_BYTES)   // 96 KB

// ---------------------------------------------------------------------------
// GEMM1 (in_proj): D[d, token] = sum_k Wh[d,k] * (xh+xl)[token,k]
// Epilogue -> g_u[b][d][l].
// ---------------------------------------------------------------------------
__global__ __launch_bounds__(NTHREADS, 1) void gemm_mma1(const __half* __restrict__ Wh,
                                                         const __half* __restrict__ Xh,
                                                         const __half* __restrict__ Xl,
                                                         const float* __restrict__ bias)
{
    extern __shared__ __align__(1024) char dyn[];
    const uint32_t sb = smem_u32(dyn);
    const int tid  = threadIdx.x;
    const int wid  = tid >> 5;
    const int lane = tid & 31;
    const int wm = wid & 3;          // 4 M-groups of 32 rows
    const int wn = wid >> 2;         // 4 N-groups of 64 cols
    const int n0 = blockIdx.x * 256; // token
    const int m0 = blockIdx.y * 128; // d

    const __half* Ah = Wh + (size_t)m0 * 512;
    const __half* Bh = Xh + (size_t)n0 * 512;
    const __half* Bl = Xl + (size_t)n0 * 512;

    auto load_stage = [&](int stage, int c) {
        const int k0 = c * 64;
        const uint32_t sbase = sb + stage * STAGE1_BYTES;
#pragma unroll
        for (int i = 0; i < 4; i++) {
            const int idx = i * NTHREADS + tid;        // 0..2047
            const int rB  = idx >> 3;                  // 0..255
            const int chB = idx & 7;
            const uint32_t soB = (uint32_t)((rB * 128 + chB * 16) ^ ((rB & 7) << 4));
            const size_t  goB = (size_t)rB * 512 + k0 + chB * 8;
            cpasync16(sbase + 16384 + soB, Bh + goB);
            cpasync16(sbase + 49152 + soB, Bl + goB);
            if (i < 2) {                               // A: 128 rows
                cpasync16(sbase + soB, Ah + goB);
            }
        }
        cp_commit();
    };

    float c[2][8][4];
#pragma unroll
    for (int mi = 0; mi < 2; mi++)
#pragma unroll
        for (int ni = 0; ni < 8; ni++)
#pragma unroll
            for (int j = 0; j < 4; j++) c[mi][ni][j] = 0.0f;

    load_stage(0, 0);
    load_stage(1, 1);

    const int grp = lane >> 3;
    const int sub = lane & 7;

#pragma unroll 1
    for (int cch = 0; cch < 8; cch++) {
        if (cch == 7) asm volatile("cp.async.wait_group 0;" ::: "memory");
        else          asm volatile("cp.async.wait_group 1;" ::: "memory");
        __syncthreads();

        const uint32_t sa = sb + (cch & 1) * STAGE1_BYTES;

#pragma unroll
        for (int s = 0; s < 4; s++) {
            uint32_t aH[2][4];
#pragma unroll
            for (int mi = 0; mi < 2; mi++) {
                const int rowA = wm * 32 + mi * 16 + (grp & 1) * 8 + sub;
                const int kbA  = s * 32 + (grp >> 1) * 16;
                const uint32_t off = (uint32_t)((rowA * 128 + kbA) ^ ((rowA & 7) << 4));
                ldsm4(sa + off, aH[mi]);
            }
#pragma unroll
            for (int p = 0; p < 4; p++) {
                uint32_t bH[4], bL[4];
                const int rowB = wn * 64 + (2 * p + (grp >> 1)) * 8 + sub;
                const int kbB  = s * 32 + (grp & 1) * 16;
                const uint32_t off = (uint32_t)((rowB * 128 + kbB) ^ ((rowB & 7) << 4));
                ldsm4(sa + 16384 + off, bH);
                ldsm4(sa + 49152 + off, bL);
#pragma unroll
                for (int mi = 0; mi < 2; mi++) {
                    mma16816(c[mi][2 * p + 0], aH[mi], &bH[0]);
                    mma16816(c[mi][2 * p + 1], aH[mi], &bH[2]);
                    mma16816(c[mi][2 * p + 0], aH[mi], &bL[0]);
                    mma16816(c[mi][2 * p + 1], aH[mi], &bL[2]);
                }
            }
        }
        __syncthreads();
        if (cch + 2 < 8) load_stage(cch & 1, cch + 2);
    }

    // epilogue: m=d rows, n=token cols -> g_u[b][d][l]
    const int q  = lane >> 2;
    const int t2 = (lane & 3) * 2;
    const int b  = n0 >> 11;
    const int lt = (n0 & 2047) + wn * 64;
#pragma unroll
    for (int mi = 0; mi < 2; mi++)
#pragma unroll
        for (int rr = 0; rr < 2; rr++) {
            const int d_row = m0 + wm * 32 + mi * 16 + rr * 8 + q;
            const float bi = __ldg(bias + d_row);
            float* dst = g_u + ((size_t)(b * DMODEL + d_row) << 11) + lt;
#pragma unroll
            for (int ni = 0; ni < 8; ni++) {
                float2 v;
                v.x = c[mi][ni][rr * 2 + 0] + bi;
                v.y = c[mi][ni][rr * 2 + 1] + bi;
                *(float2*)(dst + ni * 8 + t2) = v;
            }
        }
}

// ---------------------------------------------------------------------------
// GEMM2 (out_proj): out[token, n] = sum_k yh[token,k] * Wh[n,k]
// A = y-hi only, from K-major [b][d][l] fp16 via ldmatrix.trans (1-pass).
// ---------------------------------------------------------------------------
__global__ __launch_bounds__(NTHREADS, 1) void gemm_mma2(const __half* __restrict__ Wh,
                                                         const float* __restrict__ bias,
                                                         float* __restrict__ Cout)
{
    extern __shared__ __align__(1024) char dyn[];
    const uint32_t sb = smem_u32(dyn);
    const int tid  = threadIdx.x;
    const int wid  = tid >> 5;
    const int lane = tid & 31;
    const int wm = wid & 3;
    const int wn = wid >> 2;
    const int n0 = blockIdx.x * 256;   // d_out
    const int m0 = blockIdx.y * 128;   // token
    const int b    = m0 >> 11;
    const int ltok = m0 & 2047;

    const __half* Bh = Wh + (size_t)n0 * 512;

    auto load_stage = [&](int stage, int c) {
        const int k0 = c * 64;
        const uint32_t sbase = sb + stage * STAGE2_BYTES;
#pragma unroll
        for (int i = 0; i < 4; i++) {
            const int idx = i * NTHREADS + tid;        // 0..2047
            // B: 256 rows x 8 chunks
            const int rB  = idx >> 3;
            const int chB = idx & 7;
            const uint32_t soB = (uint32_t)((rB * 128 + chB * 16) ^ ((rB & 7) << 4));
            const size_t  goB = (size_t)rB * 512 + k0 + chB * 8;
            cpasync16(sbase + 16384 + soB, Bh + goB);
            // A (yh trans): 64 rows (k=d) x 16 chunks (m=token), 256B rows
            if (i < 2) {
                const int rA  = idx >> 4;
                const int chA = idx & 15;
                const uint32_t soA = (uint32_t)(rA * 256 + ((chA ^ (rA & 7)) << 4));
                const size_t  goA = ((size_t)(b * DMODEL + k0 + rA) << 11) + ltok + chA * 8;
                cpasync16(sbase + soA, g_yh + goA);
            }
        }
        cp_commit();
    };

    float c[2][8][4];
#pragma unroll
    for (int mi = 0; mi < 2; mi++)
#pragma unroll
        for (int ni = 0; ni < 8; ni++)
#pragma unroll
            for (int j = 0; j < 4; j++) c[mi][ni][j] = 0.0f;

    load_stage(0, 0);
    load_stage(1, 1);

    const int grp = lane >> 3;
    const int sub = lane & 7;

#pragma unroll 1
    for (int cch = 0; cch < 8; cch++) {
        if (cch == 7) asm volatile("cp.async.wait_group 0;" ::: "memory");
        else          asm volatile("cp.async.wait_group 1;" ::: "memory");
        __syncthreads();

        const uint32_t sa = sb + (cch & 1) * STAGE2_BYTES;

#pragma unroll
        for (int s = 0; s < 4; s++) {
            uint32_t aH[2][4];
#pragma unroll
            for (int mi = 0; mi < 2; mi++) {
                const int krow = s * 16 + (grp >> 1) * 8 + sub;
                const int mcol = wm * 32 + mi * 16 + (grp & 1) * 8;
                const int chunk = mcol >> 3;
                const uint32_t off = (uint32_t)(krow * 256 + ((chunk ^ (krow & 7)) << 4));
                ldsm4t(sa + off, aH[mi]);
            }
#pragma unroll
            for (int p = 0; p < 4; p++) {
                uint32_t bH[4];
                const int rowB = wn * 64 + (2 * p + (grp >> 1)) * 8 + sub;
                const int kbB  = s * 32 + (grp & 1) * 16;
                const uint32_t off = (uint32_t)((rowB * 128 + kbB) ^ ((rowB & 7) << 4));
                ldsm4(sa + 16384 + off, bH);
#pragma unroll
                for (int mi = 0; mi < 2; mi++) {
                    mma16816(c[mi][2 * p + 0], aH[mi], &bH[0]);
                    mma16816(c[mi][2 * p + 1], aH[mi], &bH[2]);
                }
            }
        }
        __syncthreads();
        if (cch + 2 < 8) load_stage(cch & 1, cch + 2);
    }

    // epilogue: row-major out
    const int q  = lane >> 2;
    const int t2 = (lane & 3) * 2;
#pragma unroll
    for (int mi = 0; mi < 2; mi++)
#pragma unroll
        for (int rr = 0; rr < 2; rr++) {
            const int row = m0 + wm * 32 + mi * 16 + rr * 8 + q;
            float* dst = Cout + (size_t)row * 512 + n0 + wn * 64;
#pragma unroll
            for (int ni = 0; ni < 8; ni++) {
                const float2 bv = *(const float2*)(bias + n0 + wn * 64 + ni * 8 + t2);
                float2 v;
                v.x = c[mi][ni][rr * 2 + 0] + bv.x;
                v.y = c[mi][ni][rr * 2 + 1] + bv.y;
                *(float2*)(dst + ni * 8 + t2) = v;
            }
        }
}

// ---------------------------------------------------------------------------
// SSM recurrence scan: one warp per (b,d); 2 states/lane.
// 64-thread CTAs (2 warps): 1024 CTAs -> ~7 CTAs/SM, near-perfect SM balance
// (vs 256x8-warp CTAs: 1.73 CTAs/SM -> 16% makespan quantization penalty).
// Writes y hi-only fp16 in [b][d][l].
// ---------------------------------------------------------------------------
__global__ __launch_bounds__(64) void s4_scan(const float* __restrict__ A_log,
                                              const float* __restrict__ Bp,
                                              const float* __restrict__ Cp,
                                              const float* __restrict__ Dp,
                                              const float* __restrict__ dt)
{
    const int warp = blockIdx.x * 2 + (threadIdx.x >> 5);
    const int lane = threadIdx.x & 31;
    const int d = warp & (DMODEL - 1);
    const int b = warp >> 9;

    const float dtd = dt[d];
    const int i0 = d * DSTATE + lane;
    const int i1 = i0 + 32;

    const float r0 = expf(-expf(A_log[i0]) * dtd);
    const float r1 = expf(-expf(A_log[i1]) * dtd);
    const float c0 = Cp[i0] * Bp[i0] * dtd;
    const float c1 = Cp[i1] * Bp[i1] * dtd;
    const float Dd = Dp[d];

    const size_t rowoff = (size_t)(b * DMODEL + d) << 11;
    const float* ub = g_u + rowoff;
    __half* yh = g_yh + rowoff;

    float z0 = 0.0f, z1 = 0.0f;

    for (int t0 = 0; t0 < SEQLEN; t0 += 32) {
        const float uv = ub[t0 + lane];
        float p[32];
#pragma unroll
        for (int i = 0; i < 32; i++) {
            const float uu = __shfl_sync(0xffffffffu, uv, i);
            z0 = fmaf(r0, z0, uu);
            z1 = fmaf(r1, z1, uu);
            p[i] = fmaf(c0, z0, c1 * z1);
        }
        const bool h16 = (lane & 16);
        float s16[16];
#pragma unroll
        for (int k = 0; k < 16; k++) {
            const float keep = h16 ? p[k + 16] : p[k];
            const float send = h16 ? p[k] : p[k + 16];
            s16[k] = keep + __shfl_xor_sync(0xffffffffu, send, 16);
        }
        const bool h8 = (lane & 8);
        float s8[8];
#pragma unroll
        for (int k = 0; k < 8; k++) {
            const float keep = h8 ? s16[k + 8] : s16[k];
            const float send = h8 ? s16[k] : s16[k + 8];
            s8[k] = keep + __shfl_xor_sync(0xffffffffu, send, 8);
        }
        const bool h4 = (lane & 4);
        float s4[4];
#pragma unroll
        for (int k = 0; k < 4; k++) {
            const float keep = h4 ? s8[k + 4] : s8[k];
            const float send = h4 ? s8[k] : s8[k + 4];
            s4[k] = keep + __shfl_xor_sync(0xffffffffu, send, 4);
        }
        const bool h2 = (lane & 2);
        float s2[2];
#pragma unroll
        for (int k = 0; k < 2; k++) {
            const float keep = h2 ? s4[k + 2] : s4[k];
            const float send = h2 ? s4[k] : s4[k + 2];
            s2[k] = keep + __shfl_xor_sync(0xffffffffu, send, 2);
        }
        const bool h1 = (lane & 1);
        const float keep = h1 ? s2[1] : s2[0];
        const float send = h1 ? s2[0] : s2[1];
        const float tot = keep + __shfl_xor_sync(0xffffffffu, send, 1);

        yh[t0 + lane] = __float2half_rn(fmaf(Dd, uv, tot));
    }
}

// ---------------------------------------------------------------------------
extern "C" void kernel_launch(void* const* d_in, const int* in_sizes, int n_in,
                              void* d_out, int out_size)
{
    const float* x     = (const float*)d_in[0];
    const float* W_in  = (const float*)d_in[1];
    const float* b_in  = (const float*)d_in[2];
    const float* A_log = (const float*)d_in[3];
    const float* B     = (const float*)d_in[4];
    const float* C     = (const float*)d_in[5];
    const float* D     = (const float*)d_in[6];
    const float* dt    = (const float*)d_in[7];
    const float* W_out = (const float*)d_in[8];
    const float* b_out = (const float*)d_in[9];
    float* out = (float*)d_out;

    static bool attr_done = false;
    if (!attr_done) {
        cudaFuncSetAttribute(gemm_mma1, cudaFuncAttributeMaxDynamicSharedMemorySize, SMEM1_BYTES);
        cudaFuncSetAttribute(gemm_mma2, cudaFuncAttributeMaxDynamicSharedMemorySize, SMEM2_BYTES);
        attr_done = true;
    }

    __half *p_ah, *p_al, *p_wh;
    cudaGetSymbolAddress((void**)&p_ah, g_ah);
    cudaGetSymbolAddress((void**)&p_al, g_al);
    cudaGetSymbolAddress((void**)&p_wh, g_wh);

    // 1) convert: x -> hi/lo, weights -> hi only (single launch)
    {
        const int total = N4_X + 2 * N4_W;
        convert_all<<<(total + 255) / 256, 256>>>(x, W_in, W_out, p_ah, p_al, p_wh);
    }

    // 2) in_proj: D[d, token] -> g_u[b][d][l]   (grid 32x4 = 128 CTAs, 1 wave)
    {
        dim3 g(MTOT / 256, DMODEL / 128);
        gemm_mma1<<<g, NTHREADS, SMEM1_BYTES>>>(p_wh, p_ah, p_al, b_in);
    }

    // 3) SSM recurrence: g_u -> g_yh  (1024 CTAs x 64 thr, SM-balanced)
    s4_scan<<<BATCH * DMODEL / 2, 64>>>(A_log, B, C, D, dt);

    // 4) out_proj: yh (trans) @ W_out_h^T -> out (grid 2x64 = 128 CTAs, 1 wave)
    {
        dim3 g(DMODEL / 256, MTOT / 128);
        gemm_mma2<<<g, NTHREADS, SMEM2_BYTES>>>(p_wh + DMODEL * DMODEL, b_out, out);
    }
}

// round 11
// speedup vs baseline: 1.5076x; 1.1157x over previous
#include <cuda_runtime.h>
#include <cuda_fp16.h>
#include <math.h>
#include <stdint.h>

// Problem constants
#define BATCH   4
#define SEQLEN  2048
#define DMODEL  512
#define DSTATE  64
#define MTOT    (BATCH * SEQLEN)   // 8192

// ---------------------------------------------------------------------------
// Device scratch (no cudaMalloc allowed)
// ---------------------------------------------------------------------------
__device__ float  g_u[BATCH * DMODEL * SEQLEN];   // [b][d][l] fp32 (scan input)
__device__ __half g_yh[BATCH * DMODEL * SEQLEN];  // [b][d][l] y hi
__device__ __half g_ah[MTOT * DMODEL];            // x hi [token][k]
__device__ __half g_wh[2 * DMODEL * DMODEL];      // W_in | W_out hi

// ---------------------------------------------------------------------------
// PTX helpers
// ---------------------------------------------------------------------------
__device__ __forceinline__ uint32_t smem_u32(const void* p) {
    uint32_t a;
    asm("{ .reg .u64 t; cvta.to.shared.u64 t, %1; cvt.u32.u64 %0, t; }" : "=r"(a) : "l"(p));
    return a;
}
__device__ __forceinline__ void cpasync16(uint32_t s, const void* g) {
    asm volatile("cp.async.cg.shared.global [%0], [%1], 16;" :: "r"(s), "l"(g));
}
__device__ __forceinline__ void cp_commit() {
    asm volatile("cp.async.commit_group;" ::: "memory");
}
__device__ __forceinline__ void ldsm4(uint32_t a, uint32_t* r) {
    asm volatile("ldmatrix.sync.aligned.m8n8.x4.shared.b16 {%0,%1,%2,%3}, [%4];"
                 : "=r"(r[0]), "=r"(r[1]), "=r"(r[2]), "=r"(r[3]) : "r"(a));
}
__device__ __forceinline__ void ldsm4t(uint32_t a, uint32_t* r) {
    asm volatile("ldmatrix.sync.aligned.m8n8.x4.trans.shared.b16 {%0,%1,%2,%3}, [%4];"
                 : "=r"(r[0]), "=r"(r[1]), "=r"(r[2]), "=r"(r[3]) : "r"(a));
}
__device__ __forceinline__ void mma16816(float* c, const uint32_t* a, const uint32_t* b) {
    asm volatile(
        "mma.sync.aligned.m16n8k16.row.col.f32.f16.f16.f32 "
        "{%0,%1,%2,%3}, {%4,%5,%6,%7}, {%8,%9}, {%0,%1,%2,%3};"
        : "+f"(c[0]), "+f"(c[1]), "+f"(c[2]), "+f"(c[3])
        : "r"(a[0]), "r"(a[1]), "r"(a[2]), "r"(a[3]), "r"(b[0]), "r"(b[1]));
}

// ---------------------------------------------------------------------------
// Conversion: x -> fp16 hi; weights -> fp16 hi. (Both lo terms dropped; the
// remaining error budget is dominated by these roundings at ~2e-4 each.)
// ---------------------------------------------------------------------------
#define N4_X (MTOT * DMODEL / 4)
#define N4_W (DMODEL * DMODEL / 4)

__global__ __launch_bounds__(256) void convert_all(const float* __restrict__ x,
                                                   const float* __restrict__ w_in,
                                                   const float* __restrict__ w_out,
                                                   __half* __restrict__ ah,
                                                   __half* __restrict__ wh)
{
    int i = blockIdx.x * 256 + threadIdx.x;
    if (i < N4_X) {
        float4 v = ((const float4*)x)[i];
        uint2 ph;
        ph.x = (uint32_t)__half_as_ushort(__float2half_rn(v.x)) |
               ((uint32_t)__half_as_ushort(__float2half_rn(v.y)) << 16);
        ph.y = (uint32_t)__half_as_ushort(__float2half_rn(v.z)) |
               ((uint32_t)__half_as_ushort(__float2half_rn(v.w)) << 16);
        ((uint2*)ah)[i] = ph;
    } else if (i < N4_X + 2 * N4_W) {
        const int off = i - N4_X;
        const float4 v = (off < N4_W) ? ((const float4*)w_in)[off]
                                      : ((const float4*)w_out)[off - N4_W];
        uint2 ph;
        ph.x = (uint32_t)__half_as_ushort(__float2half_rn(v.x)) |
               ((uint32_t)__half_as_ushort(__float2half_rn(v.y)) << 16);
        ph.y = (uint32_t)__half_as_ushort(__float2half_rn(v.z)) |
               ((uint32_t)__half_as_ushort(__float2half_rn(v.w)) << 16);
        ((uint2*)wh)[off] = ph;
    }
}

// ---------------------------------------------------------------------------
// GEMM config: CTA tile 128(M) x 256(N), K-chunk 64, 2 stages, 16 warps 4x4,
// warp tile 32x64. Single wave: grid = 128 CTAs. 1-pass fp16.
// ---------------------------------------------------------------------------
#define NTHREADS 512

// GEMM1 stage: Wh(A) 16KB @0, xh(B) 32KB @16384 -> 48KB
#define STAGE1_BYTES 49152
#define SMEM1_BYTES  (2 * STAGE1_BYTES)   // 96 KB
// GEMM2 stage: yh(A) 16KB @0, Wh(B) 32KB @16384 -> 48KB
#define STAGE2_BYTES 49152
#define SMEM2_BYTES  (2 * STAGE2_BYTES)   // 96 KB

// ---------------------------------------------------------------------------
// GEMM1 (in_proj): D[d, token] = sum_k Wh[d,k] * xh[token,k]
// Epilogue -> g_u[b][d][l].
// ---------------------------------------------------------------------------
__global__ __launch_bounds__(NTHREADS, 1) void gemm_mma1(const __half* __restrict__ Wh,
                                                         const __half* __restrict__ Xh,
                                                         const float* __restrict__ bias)
{
    extern __shared__ __align__(1024) char dyn[];
    const uint32_t sb = smem_u32(dyn);
    const int tid  = threadIdx.x;
    const int wid  = tid >> 5;
    const int lane = tid & 31;
    const int wm = wid & 3;          // 4 M-groups of 32 rows
    const int wn = wid >> 2;         // 4 N-groups of 64 cols
    const int n0 = blockIdx.x * 256; // token
    const int m0 = blockIdx.y * 128; // d

    const __half* Ah = Wh + (size_t)m0 * 512;
    const __half* Bh = Xh + (size_t)n0 * 512;

    auto load_stage = [&](int stage, int c) {
        const int k0 = c * 64;
        const uint32_t sbase = sb + stage * STAGE1_BYTES;
#pragma unroll
        for (int i = 0; i < 4; i++) {
            const int idx = i * NTHREADS + tid;        // 0..2047
            const int rB  = idx >> 3;                  // 0..255
            const int chB = idx & 7;
            const uint32_t soB = (uint32_t)((rB * 128 + chB * 16) ^ ((rB & 7) << 4));
            const size_t  goB = (size_t)rB * 512 + k0 + chB * 8;
            cpasync16(sbase + 16384 + soB, Bh + goB);
            if (i < 2) {                               // A: 128 rows
                cpasync16(sbase + soB, Ah + goB);
            }
        }
        cp_commit();
    };

    float c[2][8][4];
#pragma unroll
    for (int mi = 0; mi < 2; mi++)
#pragma unroll
        for (int ni = 0; ni < 8; ni++)
#pragma unroll
            for (int j = 0; j < 4; j++) c[mi][ni][j] = 0.0f;

    load_stage(0, 0);
    load_stage(1, 1);

    const int grp = lane >> 3;
    const int sub = lane & 7;

#pragma unroll 1
    for (int cch = 0; cch < 8; cch++) {
        if (cch == 7) asm volatile("cp.async.wait_group 0;" ::: "memory");
        else          asm volatile("cp.async.wait_group 1;" ::: "memory");
        __syncthreads();

        const uint32_t sa = sb + (cch & 1) * STAGE1_BYTES;

#pragma unroll
        for (int s = 0; s < 4; s++) {
            uint32_t aH[2][4];
#pragma unroll
            for (int mi = 0; mi < 2; mi++) {
                const int rowA = wm * 32 + mi * 16 + (grp & 1) * 8 + sub;
                const int kbA  = s * 32 + (grp >> 1) * 16;
                const uint32_t off = (uint32_t)((rowA * 128 + kbA) ^ ((rowA & 7) << 4));
                ldsm4(sa + off, aH[mi]);
            }
#pragma unroll
            for (int p = 0; p < 4; p++) {
                uint32_t bH[4];
                const int rowB = wn * 64 + (2 * p + (grp >> 1)) * 8 + sub;
                const int kbB  = s * 32 + (grp & 1) * 16;
                const uint32_t off = (uint32_t)((rowB * 128 + kbB) ^ ((rowB & 7) << 4));
                ldsm4(sa + 16384 + off, bH);
#pragma unroll
                for (int mi = 0; mi < 2; mi++) {
                    mma16816(c[mi][2 * p + 0], aH[mi], &bH[0]);
                    mma16816(c[mi][2 * p + 1], aH[mi], &bH[2]);
                }
            }
        }
        __syncthreads();
        if (cch + 2 < 8) load_stage(cch & 1, cch + 2);
    }

    // epilogue: m=d rows, n=token cols -> g_u[b][d][l]
    const int q  = lane >> 2;
    const int t2 = (lane & 3) * 2;
    const int b  = n0 >> 11;
    const int lt = (n0 & 2047) + wn * 64;
#pragma unroll
    for (int mi = 0; mi < 2; mi++)
#pragma unroll
        for (int rr = 0; rr < 2; rr++) {
            const int d_row = m0 + wm * 32 + mi * 16 + rr * 8 + q;
            const float bi = __ldg(bias + d_row);
            float* dst = g_u + ((size_t)(b * DMODEL + d_row) << 11) + lt;
#pragma unroll
            for (int ni = 0; ni < 8; ni++) {
                float2 v;
                v.x = c[mi][ni][rr * 2 + 0] + bi;
                v.y = c[mi][ni][rr * 2 + 1] + bi;
                *(float2*)(dst + ni * 8 + t2) = v;
            }
        }
}

// ---------------------------------------------------------------------------
// GEMM2 (out_proj): out[token, n] = sum_k yh[token,k] * Wh[n,k]
// A = y-hi from K-major [b][d][l] fp16 via ldmatrix.trans (1-pass).
// ---------------------------------------------------------------------------
__global__ __launch_bounds__(NTHREADS, 1) void gemm_mma2(const __half* __restrict__ Wh,
                                                         const float* __restrict__ bias,
                                                         float* __restrict__ Cout)
{
    extern __shared__ __align__(1024) char dyn[];
    const uint32_t sb = smem_u32(dyn);
    const int tid  = threadIdx.x;
    const int wid  = tid >> 5;
    const int lane = tid & 31;
    const int wm = wid & 3;
    const int wn = wid >> 2;
    const int n0 = blockIdx.x * 256;   // d_out
    const int m0 = blockIdx.y * 128;   // token
    const int b    = m0 >> 11;
    const int ltok = m0 & 2047;

    const __half* Bh = Wh + (size_t)n0 * 512;

    auto load_stage = [&](int stage, int c) {
        const int k0 = c * 64;
        const uint32_t sbase = sb + stage * STAGE2_BYTES;
#pragma unroll
        for (int i = 0; i < 4; i++) {
            const int idx = i * NTHREADS + tid;        // 0..2047
            const int rB  = idx >> 3;
            const int chB = idx & 7;
            const uint32_t soB = (uint32_t)((rB * 128 + chB * 16) ^ ((rB & 7) << 4));
            const size_t  goB = (size_t)rB * 512 + k0 + chB * 8;
            cpasync16(sbase + 16384 + soB, Bh + goB);
            if (i < 2) {
                const int rA  = idx >> 4;
                const int chA = idx & 15;
                const uint32_t soA = (uint32_t)(rA * 256 + ((chA ^ (rA & 7)) << 4));
                const size_t  goA = ((size_t)(b * DMODEL + k0 + rA) << 11) + ltok + chA * 8;
                cpasync16(sbase + soA, g_yh + goA);
            }
        }
        cp_commit();
    };

    float c[2][8][4];
#pragma unroll
    for (int mi = 0; mi < 2; mi++)
#pragma unroll
        for (int ni = 0; ni < 8; ni++)
#pragma unroll
            for (int j = 0; j < 4; j++) c[mi][ni][j] = 0.0f;

    load_stage(0, 0);
    load_stage(1, 1);

    const int grp = lane >> 3;
    const int sub = lane & 7;

#pragma unroll 1
    for (int cch = 0; cch < 8; cch++) {
        if (cch == 7) asm volatile("cp.async.wait_group 0;" ::: "memory");
        else          asm volatile("cp.async.wait_group 1;" ::: "memory");
        __syncthreads();

        const uint32_t sa = sb + (cch & 1) * STAGE2_BYTES;

#pragma unroll
        for (int s = 0; s < 4; s++) {
            uint32_t aH[2][4];
#pragma unroll
            for (int mi = 0; mi < 2; mi++) {
                const int krow = s * 16 + (grp >> 1) * 8 + sub;
                const int mcol = wm * 32 + mi * 16 + (grp & 1) * 8;
                const int chunk = mcol >> 3;
                const uint32_t off = (uint32_t)(krow * 256 + ((chunk ^ (krow & 7)) << 4));
                ldsm4t(sa + off, aH[mi]);
            }
#pragma unroll
            for (int p = 0; p < 4; p++) {
                uint32_t bH[4];
                const int rowB = wn * 64 + (2 * p + (grp >> 1)) * 8 + sub;
                const int kbB  = s * 32 + (grp & 1) * 16;
                const uint32_t off = (uint32_t)((rowB * 128 + kbB) ^ ((rowB & 7) << 4));
                ldsm4(sa + 16384 + off, bH);
#pragma unroll
                for (int mi = 0; mi < 2; mi++) {
                    mma16816(c[mi][2 * p + 0], aH[mi], &bH[0]);
                    mma16816(c[mi][2 * p + 1], aH[mi], &bH[2]);
                }
            }
        }
        __syncthreads();
        if (cch + 2 < 8) load_stage(cch & 1, cch + 2);
    }

    // epilogue: row-major out
    const int q  = lane >> 2;
    const int t2 = (lane & 3) * 2;
#pragma unroll
    for (int mi = 0; mi < 2; mi++)
#pragma unroll
        for (int rr = 0; rr < 2; rr++) {
            const int row = m0 + wm * 32 + mi * 16 + rr * 8 + q;
            float* dst = Cout + (size_t)row * 512 + n0 + wn * 64;
#pragma unroll
            for (int ni = 0; ni < 8; ni++) {
                const float2 bv = *(const float2*)(bias + n0 + wn * 64 + ni * 8 + t2);
                float2 v;
                v.x = c[mi][ni][rr * 2 + 0] + bv.x;
                v.y = c[mi][ni][rr * 2 + 1] + bv.y;
                *(float2*)(dst + ni * 8 + t2) = v;
            }
        }
}

// ---------------------------------------------------------------------------
// SSM recurrence scan: one warp per (b,d); 2 states/lane. 64-thread CTAs for
// SM balance. Broadcast u values come from uniform vector loads (all lanes
// load the same L1 line -> HW broadcast), replacing 32 shuffles per chunk.
// ---------------------------------------------------------------------------
__global__ __launch_bounds__(64) void s4_scan(const float* __restrict__ A_log,
                                              const float* __restrict__ Bp,
                                              const float* __restrict__ Cp,
                                              const float* __restrict__ Dp,
                                              const float* __restrict__ dt)
{
    const int warp = blockIdx.x * 2 + (threadIdx.x >> 5);
    const int lane = threadIdx.x & 31;
    const int d = warp & (DMODEL - 1);
    const int b = warp >> 9;

    const float dtd = dt[d];
    const int i0 = d * DSTATE + lane;
    const int i1 = i0 + 32;

    const float r0 = expf(-expf(A_log[i0]) * dtd);
    const float r1 = expf(-expf(A_log[i1]) * dtd);
    const float c0 = Cp[i0] * Bp[i0] * dtd;
    const float c1 = Cp[i1] * Bp[i1] * dtd;
    const float Dd = Dp[d];

    const size_t rowoff = (size_t)(b * DMODEL + d) << 11;
    const float* ub = g_u + rowoff;
    __half* yh = g_yh + rowoff;

    float z0 = 0.0f, z1 = 0.0f;

    for (int t0 = 0; t0 < SEQLEN; t0 += 32) {
        // uniform broadcast loads of the chunk's 32 u values
        float4 uu4[8];
        const float4* ub4 = (const float4*)(ub + t0);
#pragma unroll
        for (int j = 0; j < 8; j++) uu4[j] = ub4[j];
        const float uv = ub[t0 + lane];   // this lane's own u (for D-skip)

        float p[32];
#pragma unroll
        for (int i = 0; i < 32; i++) {
            const float uu = (i & 3) == 0 ? uu4[i >> 2].x
                           : (i & 3) == 1 ? uu4[i >> 2].y
                           : (i & 3) == 2 ? uu4[i >> 2].z
                                          : uu4[i >> 2].w;
            z0 = fmaf(r0, z0, uu);
            z1 = fmaf(r1, z1, uu);
            p[i] = fmaf(c0, z0, c1 * z1);
        }
        const bool h16 = (lane & 16);
        float s16[16];
#pragma unroll
        for (int k = 0; k < 16; k++) {
            const float keep = h16 ? p[k + 16] : p[k];
            const float send = h16 ? p[k] : p[k + 16];
            s16[k] = keep + __shfl_xor_sync(0xffffffffu, send, 16);
        }
        const bool h8 = (lane & 8);
        float s8[8];
#pragma unroll
        for (int k = 0; k < 8; k++) {
            const float keep = h8 ? s16[k + 8] : s16[k];
            const float send = h8 ? s16[k] : s16[k + 8];
            s8[k] = keep + __shfl_xor_sync(0xffffffffu, send, 8);
        }
        const bool h4 = (lane & 4);
        float s4[4];
#pragma unroll
        for (int k = 0; k < 4; k++) {
            const float keep = h4 ? s8[k + 4] : s8[k];
            const float send = h4 ? s8[k] : s8[k + 4];
            s4[k] = keep + __shfl_xor_sync(0xffffffffu, send, 4);
        }
        const bool h2 = (lane & 2);
        float s2[2];
#pragma unroll
        for (int k = 0; k < 2; k++) {
            const float keep = h2 ? s4[k + 2] : s4[k];
            const float send = h2 ? s4[k] : s4[k + 2];
            s2[k] = keep + __shfl_xor_sync(0xffffffffu, send, 2);
        }
        const bool h1 = (lane & 1);
        const float keep = h1 ? s2[1] : s2[0];
        const float send = h1 ? s2[0] : s2[1];
        const float tot = keep + __shfl_xor_sync(0xffffffffu, send, 1);

        yh[t0 + lane] = __float2half_rn(fmaf(Dd, uv, tot));
    }
}

// ---------------------------------------------------------------------------
extern "C" void kernel_launch(void* const* d_in, const int* in_sizes, int n_in,
                              void* d_out, int out_size)
{
    const float* x     = (const float*)d_in[0];
    const float* W_in  = (const float*)d_in[1];
    const float* b_in  = (const float*)d_in[2];
    const float* A_log = (const float*)d_in[3];
    const float* B     = (const float*)d_in[4];
    const float* C     = (const float*)d_in[5];
    const float* D     = (const float*)d_in[6];
    const float* dt    = (const float*)d_in[7];
    const float* W_out = (const float*)d_in[8];
    const float* b_out = (const float*)d_in[9];
    float* out = (float*)d_out;

    static bool attr_done = false;
    if (!attr_done) {
        cudaFuncSetAttribute(gemm_mma1, cudaFuncAttributeMaxDynamicSharedMemorySize, SMEM1_BYTES);
        cudaFuncSetAttribute(gemm_mma2, cudaFuncAttributeMaxDynamicSharedMemorySize, SMEM2_BYTES);
        attr_done = true;
    }

    __half *p_ah, *p_wh;
    cudaGetSymbolAddress((void**)&p_ah, g_ah);
    cudaGetSymbolAddress((void**)&p_wh, g_wh);

    // 1) convert: x -> hi, weights -> hi (single launch)
    {
        const int total = N4_X + 2 * N4_W;
        convert_all<<<(total + 255) / 256, 256>>>(x, W_in, W_out, p_ah, p_wh);
    }

    // 2) in_proj: D[d, token] -> g_u[b][d][l]   (grid 32x4 = 128 CTAs, 1 wave)
    {
        dim3 g(MTOT / 256, DMODEL / 128);
        gemm_mma1<<<g, NTHREADS, SMEM1_BYTES>>>(p_wh, p_ah, b_in);
    }

    // 3) SSM recurrence: g_u -> g_yh  (1024 CTAs x 64 thr, SM-balanced)
    s4_scan<<<BATCH * DMODEL / 2, 64>>>(A_log, B, C, D, dt);

    // 4) out_proj: yh (trans) @ W_out_h^T -> out (grid 2x64 = 128 CTAs, 1 wave)
    {
        dim3 g(DMODEL / 256, MTOT / 128);
        gemm_mma2<<<g, NTHREADS, SMEM2_BYTES>>>(p_wh + DMODEL * DMODEL, b_out, out);
    }
}

// round 12
// speedup vs baseline: 1.5711x; 1.0421x over previous
#include <cuda_runtime.h>
#include <cuda_fp16.h>
#include <math.h>
#include <stdint.h>

// Problem constants
#define BATCH   4
#define SEQLEN  2048
#define DMODEL  512
#define DSTATE  64
#define MTOT    (BATCH * SEQLEN)   // 8192

// ---------------------------------------------------------------------------
// Device scratch (no cudaMalloc allowed)
// ---------------------------------------------------------------------------
__device__ float  g_u[BATCH * DMODEL * SEQLEN];   // [b][d][l] fp32 (scan input)
__device__ __half g_yh[BATCH * DMODEL * SEQLEN];  // [b][d][l] y hi
__device__ __half g_ah[MTOT * DMODEL];            // x hi [token][k]
__device__ __half g_wh[2 * DMODEL * DMODEL];      // W_in | W_out hi

// ---------------------------------------------------------------------------
// PTX helpers
// ---------------------------------------------------------------------------
__device__ __forceinline__ uint32_t smem_u32(const void* p) {
    uint32_t a;
    asm("{ .reg .u64 t; cvta.to.shared.u64 t, %1; cvt.u32.u64 %0, t; }" : "=r"(a) : "l"(p));
    return a;
}
__device__ __forceinline__ void cpasync16(uint32_t s, const void* g) {
    asm volatile("cp.async.cg.shared.global [%0], [%1], 16;" :: "r"(s), "l"(g));
}
__device__ __forceinline__ void cp_commit() {
    asm volatile("cp.async.commit_group;" ::: "memory");
}
__device__ __forceinline__ void ldsm4(uint32_t a, uint32_t* r) {
    asm volatile("ldmatrix.sync.aligned.m8n8.x4.shared.b16 {%0,%1,%2,%3}, [%4];"
                 : "=r"(r[0]), "=r"(r[1]), "=r"(r[2]), "=r"(r[3]) : "r"(a));
}
__device__ __forceinline__ void ldsm4t(uint32_t a, uint32_t* r) {
    asm volatile("ldmatrix.sync.aligned.m8n8.x4.trans.shared.b16 {%0,%1,%2,%3}, [%4];"
                 : "=r"(r[0]), "=r"(r[1]), "=r"(r[2]), "=r"(r[3]) : "r"(a));
}
__device__ __forceinline__ void mma16816(float* c, const uint32_t* a, const uint32_t* b) {
    asm volatile(
        "mma.sync.aligned.m16n8k16.row.col.f32.f16.f16.f32 "
        "{%0,%1,%2,%3}, {%4,%5,%6,%7}, {%8,%9}, {%0,%1,%2,%3};"
        : "+f"(c[0]), "+f"(c[1]), "+f"(c[2]), "+f"(c[3])
        : "r"(a[0]), "r"(a[1]), "r"(a[2]), "r"(a[3]), "r"(b[0]), "r"(b[1]));
}

// ---------------------------------------------------------------------------
// Conversion: x -> fp16 hi; weights -> fp16 hi.
// ---------------------------------------------------------------------------
#define N4_X (MTOT * DMODEL / 4)
#define N4_W (DMODEL * DMODEL / 4)

__global__ __launch_bounds__(256) void convert_all(const float* __restrict__ x,
                                                   const float* __restrict__ w_in,
                                                   const float* __restrict__ w_out,
                                                   __half* __restrict__ ah,
                                                   __half* __restrict__ wh)
{
    int i = blockIdx.x * 256 + threadIdx.x;
    if (i < N4_X) {
        float4 v = ((const float4*)x)[i];
        uint2 ph;
        ph.x = (uint32_t)__half_as_ushort(__float2half_rn(v.x)) |
               ((uint32_t)__half_as_ushort(__float2half_rn(v.y)) << 16);
        ph.y = (uint32_t)__half_as_ushort(__float2half_rn(v.z)) |
               ((uint32_t)__half_as_ushort(__float2half_rn(v.w)) << 16);
        ((uint2*)ah)[i] = ph;
    } else if (i < N4_X + 2 * N4_W) {
        const int off = i - N4_X;
        const float4 v = (off < N4_W) ? ((const float4*)w_in)[off]
                                      : ((const float4*)w_out)[off - N4_W];
        uint2 ph;
        ph.x = (uint32_t)__half_as_ushort(__float2half_rn(v.x)) |
               ((uint32_t)__half_as_ushort(__float2half_rn(v.y)) << 16);
        ph.y = (uint32_t)__half_as_ushort(__float2half_rn(v.z)) |
               ((uint32_t)__half_as_ushort(__float2half_rn(v.w)) << 16);
        ((uint2*)wh)[off] = ph;
    }
}

// ---------------------------------------------------------------------------
// GEMM config: CTA tile 128(M) x 256(N), K-chunk 128, 4 chunks, 2 stages.
// Stage: A 32KB @0, B 64KB @32768 -> 96KB; x2 = 192KB. 16 warps 4x4, warp
// tile 32x64. Single wave (128 CTAs). Per-chunk compute (~1024 cyc) covers
// DRAM latency under double buffering; 4 barrier pairs instead of 8.
// ---------------------------------------------------------------------------
#define NTHREADS 512
#define STAGE_BYTES 98304
#define SMEM_BYTES  (2 * STAGE_BYTES)   // 192 KB

// ---------------------------------------------------------------------------
// GEMM1 (in_proj): D[d, token] = sum_k Wh[d,k] * xh[token,k]
// Epilogue -> g_u[b][d][l].
// ---------------------------------------------------------------------------
__global__ __launch_bounds__(NTHREADS, 1) void gemm_mma1(const __half* __restrict__ Wh,
                                                         const __half* __restrict__ Xh,
                                                         const float* __restrict__ bias)
{
    extern __shared__ __align__(1024) char dyn[];
    const uint32_t sb = smem_u32(dyn);
    const int tid  = threadIdx.x;
    const int wid  = tid >> 5;
    const int lane = tid & 31;
    const int wm = wid & 3;          // 4 M-groups of 32 rows
    const int wn = wid >> 2;         // 4 N-groups of 64 cols
    const int n0 = blockIdx.x * 256; // token
    const int m0 = blockIdx.y * 128; // d

    const __half* Ah = Wh + (size_t)m0 * 512;
    const __half* Bh = Xh + (size_t)n0 * 512;

    auto load_stage = [&](int stage, int c) {
        const int k0 = c * 128;
        const uint32_t sbase = sb + stage * STAGE_BYTES;
#pragma unroll
        for (int i = 0; i < 8; i++) {
            const int idx = i * NTHREADS + tid;        // 0..4095
            const int r  = idx >> 4;                   // row
            const int ch = idx & 15;                   // 16B chunk in 256B row
            const uint32_t so = (uint32_t)(r * 256 + ((ch ^ (r & 7)) << 4));
            const size_t  go = (size_t)r * 512 + k0 + ch * 8;
            cpasync16(sbase + 32768 + so, Bh + go);    // B: 256 rows
            if (i < 4) cpasync16(sbase + so, Ah + go); // A: 128 rows
        }
        cp_commit();
    };

    float c[2][8][4];
#pragma unroll
    for (int mi = 0; mi < 2; mi++)
#pragma unroll
        for (int ni = 0; ni < 8; ni++)
#pragma unroll
            for (int j = 0; j < 4; j++) c[mi][ni][j] = 0.0f;

    load_stage(0, 0);
    load_stage(1, 1);

    const int grp = lane >> 3;
    const int sub = lane & 7;

#pragma unroll 1
    for (int cch = 0; cch < 4; cch++) {
        if (cch == 3) asm volatile("cp.async.wait_group 0;" ::: "memory");
        else          asm volatile("cp.async.wait_group 1;" ::: "memory");
        __syncthreads();

        const uint32_t sa = sb + (cch & 1) * STAGE_BYTES;

#pragma unroll
        for (int s = 0; s < 8; s++) {
            uint32_t aH[2][4];
#pragma unroll
            for (int mi = 0; mi < 2; mi++) {
                const int rowA = wm * 32 + mi * 16 + (grp & 1) * 8 + sub;
                const int kcA  = s * 2 + (grp >> 1);   // 16B chunk index
                const uint32_t off = (uint32_t)(rowA * 256 + ((kcA ^ (rowA & 7)) << 4));
                ldsm4(sa + off, aH[mi]);
            }
#pragma unroll
            for (int p = 0; p < 4; p++) {
                uint32_t bH[4];
                const int rowB = wn * 64 + (2 * p + (grp >> 1)) * 8 + sub;
                const int kcB  = s * 2 + (grp & 1);
                const uint32_t off = (uint32_t)(rowB * 256 + ((kcB ^ (rowB & 7)) << 4));
                ldsm4(sa + 32768 + off, bH);
#pragma unroll
                for (int mi = 0; mi < 2; mi++) {
                    mma16816(c[mi][2 * p + 0], aH[mi], &bH[0]);
                    mma16816(c[mi][2 * p + 1], aH[mi], &bH[2]);
                }
            }
        }
        __syncthreads();
        if (cch + 2 < 4) load_stage(cch & 1, cch + 2);
    }

    // epilogue: m=d rows, n=token cols -> g_u[b][d][l]
    const int q  = lane >> 2;
    const int t2 = (lane & 3) * 2;
    const int b  = n0 >> 11;
    const int lt = (n0 & 2047) + wn * 64;
#pragma unroll
    for (int mi = 0; mi < 2; mi++)
#pragma unroll
        for (int rr = 0; rr < 2; rr++) {
            const int d_row = m0 + wm * 32 + mi * 16 + rr * 8 + q;
            const float bi = __ldg(bias + d_row);
            float* dst = g_u + ((size_t)(b * DMODEL + d_row) << 11) + lt;
#pragma unroll
            for (int ni = 0; ni < 8; ni++) {
                float2 v;
                v.x = c[mi][ni][rr * 2 + 0] + bi;
                v.y = c[mi][ni][rr * 2 + 1] + bi;
                *(float2*)(dst + ni * 8 + t2) = v;
            }
        }
}

// ---------------------------------------------------------------------------
// GEMM2 (out_proj): out[token, n] = sum_k yh[token,k] * Wh[n,k]
// A = y-hi from K-major [b][d][l] via ldmatrix.trans; [128 k][128 m] tile.
// ---------------------------------------------------------------------------
__global__ __launch_bounds__(NTHREADS, 1) void gemm_mma2(const __half* __restrict__ Wh,
                                                         const float* __restrict__ bias,
                                                         float* __restrict__ Cout)
{
    extern __shared__ __align__(1024) char dyn[];
    const uint32_t sb = smem_u32(dyn);
    const int tid  = threadIdx.x;
    const int wid  = tid >> 5;
    const int lane = tid & 31;
    const int wm = wid & 3;
    const int wn = wid >> 2;
    const int n0 = blockIdx.x * 256;   // d_out
    const int m0 = blockIdx.y * 128;   // token
    const int b    = m0 >> 11;
    const int ltok = m0 & 2047;

    const __half* Bh = Wh + (size_t)n0 * 512;

    auto load_stage = [&](int stage, int c) {
        const int k0 = c * 128;
        const uint32_t sbase = sb + stage * STAGE_BYTES;
#pragma unroll
        for (int i = 0; i < 8; i++) {
            const int idx = i * NTHREADS + tid;        // 0..4095
            // B: 256 rows x 16 chunks
            const int rB  = idx >> 4;
            const int chB = idx & 15;
            const uint32_t soB = (uint32_t)(rB * 256 + ((chB ^ (rB & 7)) << 4));
            const size_t  goB = (size_t)rB * 512 + k0 + chB * 8;
            cpasync16(sbase + 32768 + soB, Bh + goB);
            // A (yh trans): 128 rows (k=d) x 16 chunks (m=token), 256B rows
            if (i < 4) {
                cpasync16(sbase + soB,
                          g_yh + (((size_t)(b * DMODEL + k0 + rB)) << 11) + ltok + chB * 8);
            }
        }
        cp_commit();
    };

    float c[2][8][4];
#pragma unroll
    for (int mi = 0; mi < 2; mi++)
#pragma unroll
        for (int ni = 0; ni < 8; ni++)
#pragma unroll
            for (int j = 0; j < 4; j++) c[mi][ni][j] = 0.0f;

    load_stage(0, 0);
    load_stage(1, 1);

    const int grp = lane >> 3;
    const int sub = lane & 7;

#pragma unroll 1
    for (int cch = 0; cch < 4; cch++) {
        if (cch == 3) asm volatile("cp.async.wait_group 0;" ::: "memory");
        else          asm volatile("cp.async.wait_group 1;" ::: "memory");
        __syncthreads();

        const uint32_t sa = sb + (cch & 1) * STAGE_BYTES;

#pragma unroll
        for (int s = 0; s < 8; s++) {
            uint32_t aH[2][4];
#pragma unroll
            for (int mi = 0; mi < 2; mi++) {
                const int krow = s * 16 + (grp >> 1) * 8 + sub;       // 0..127
                const int mcol = wm * 32 + mi * 16 + (grp & 1) * 8;
                const int chunk = mcol >> 3;                          // 0..15
                const uint32_t off = (uint32_t)(krow * 256 + ((chunk ^ (krow & 7)) << 4));
                ldsm4t(sa + off, aH[mi]);
            }
#pragma unroll
            for (int p = 0; p < 4; p++) {
                uint32_t bH[4];
                const int rowB = wn * 64 + (2 * p + (grp >> 1)) * 8 + sub;
                const int kcB  = s * 2 + (grp & 1);
                const uint32_t off = (uint32_t)(rowB * 256 + ((kcB ^ (rowB & 7)) << 4));
                ldsm4(sa + 32768 + off, bH);
#pragma unroll
                for (int mi = 0; mi < 2; mi++) {
                    mma16816(c[mi][2 * p + 0], aH[mi], &bH[0]);
                    mma16816(c[mi][2 * p + 1], aH[mi], &bH[2]);
                }
            }
        }
        __syncthreads();
        if (cch + 2 < 4) load_stage(cch & 1, cch + 2);
    }

    // epilogue: row-major out
    const int q  = lane >> 2;
    const int t2 = (lane & 3) * 2;
#pragma unroll
    for (int mi = 0; mi < 2; mi++)
#pragma unroll
        for (int rr = 0; rr < 2; rr++) {
            const int row = m0 + wm * 32 + mi * 16 + rr * 8 + q;
            float* dst = Cout + (size_t)row * 512 + n0 + wn * 64;
#pragma unroll
            for (int ni = 0; ni < 8; ni++) {
                const float2 bv = *(const float2*)(bias + n0 + wn * 64 + ni * 8 + t2);
                float2 v;
                v.x = c[mi][ni][rr * 2 + 0] + bv.x;
                v.y = c[mi][ni][rr * 2 + 1] + bv.y;
                *(float2*)(dst + ni * 8 + t2) = v;
            }
        }
}

// ---------------------------------------------------------------------------
// SSM recurrence scan, 2-segment parallel decomposition.
// Each (b,d) sequence is handled by TWO warps: seg0 does t=[0,1152) full;
// seg1 replays t=[0,1152) z-only (exact same fma sequence -> bitwise-identical
// state) then does t=[1152,2048) full. 128-thread CTAs feed all 4 SMSPs;
// 1024 CTAs ~= 6.9/SM (balanced); 6.9 warps/SMSP hides latency.
// ---------------------------------------------------------------------------
#define SPLIT_T 1152   // 36 chunks; balances seg0 (36 full) vs seg1 (36 zonly + 28 full)

__global__ __launch_bounds__(128) void s4_scan(const float* __restrict__ A_log,
                                               const float* __restrict__ Bp,
                                               const float* __restrict__ Cp,
                                               const float* __restrict__ Dp,
                                               const float* __restrict__ dt)
{
    const int wid  = threadIdx.x >> 5;
    const int lane = threadIdx.x & 31;
    const int gw   = blockIdx.x * 4 + wid;
    const int seq  = gw >> 1;
    const int seg  = gw & 1;
    const int d = seq & (DMODEL - 1);
    const int b = seq >> 9;

    const float dtd = dt[d];
    const int i0 = d * DSTATE + lane;
    const int i1 = i0 + 32;

    const float r0 = expf(-expf(A_log[i0]) * dtd);
    const float r1 = expf(-expf(A_log[i1]) * dtd);
    const float c0 = Cp[i0] * Bp[i0] * dtd;
    const float c1 = Cp[i1] * Bp[i1] * dtd;
    const float Dd = Dp[d];

    const size_t rowoff = (size_t)(b * DMODEL + d) << 11;
    const float* ub = g_u + rowoff;
    __half* yh = g_yh + rowoff;

    float z0 = 0.0f, z1 = 0.0f;

    if (seg == 1) {
        // z-only prefix over [0, SPLIT_T): identical fma order -> exact state
#pragma unroll 1
        for (int t0 = 0; t0 < SPLIT_T; t0 += 32) {
            float4 uu4[8];
            const float4* ub4 = (const float4*)(ub + t0);
#pragma unroll
            for (int j = 0; j < 8; j++) uu4[j] = ub4[j];
#pragma unroll
            for (int i = 0; i < 32; i++) {
                const float uu = (i & 3) == 0 ? uu4[i >> 2].x
                               : (i & 3) == 1 ? uu4[i >> 2].y
                               : (i & 3) == 2 ? uu4[i >> 2].z
                                              : uu4[i >> 2].w;
                z0 = fmaf(r0, z0, uu);
                z1 = fmaf(r1, z1, uu);
            }
        }
    }

    const int tbeg = seg ? SPLIT_T : 0;
    const int tend = seg ? SEQLEN : SPLIT_T;

#pragma unroll 1
    for (int t0 = tbeg; t0 < tend; t0 += 32) {
        float4 uu4[8];
        const float4* ub4 = (const float4*)(ub + t0);
#pragma unroll
        for (int j = 0; j < 8; j++) uu4[j] = ub4[j];
        const float uv = ub[t0 + lane];

        float p[32];
#pragma unroll
        for (int i = 0; i < 32; i++) {
            const float uu = (i & 3) == 0 ? uu4[i >> 2].x
                           : (i & 3) == 1 ? uu4[i >> 2].y
                           : (i & 3) == 2 ? uu4[i >> 2].z
                                          : uu4[i >> 2].w;
            z0 = fmaf(r0, z0, uu);
            z1 = fmaf(r1, z1, uu);
            p[i] = fmaf(c0, z0, c1 * z1);
        }
        const bool h16 = (lane & 16);
        float s16[16];
#pragma unroll
        for (int k = 0; k < 16; k++) {
            const float keep = h16 ? p[k + 16] : p[k];
            const float send = h16 ? p[k] : p[k + 16];
            s16[k] = keep + __shfl_xor_sync(0xffffffffu, send, 16);
        }
        const bool h8 = (lane & 8);
        float s8[8];
#pragma unroll
        for (int k = 0; k < 8; k++) {
            const float keep = h8 ? s16[k + 8] : s16[k];
            const float send = h8 ? s16[k] : s16[k + 8];
            s8[k] = keep + __shfl_xor_sync(0xffffffffu, send, 8);
        }
        const bool h4 = (lane & 4);
        float s4[4];
#pragma unroll
        for (int k = 0; k < 4; k++) {
            const float keep = h4 ? s8[k + 4] : s8[k];
            const float send = h4 ? s8[k] : s8[k + 4];
            s4[k] = keep + __shfl_xor_sync(0xffffffffu, send, 4);
        }
        const bool h2 = (lane & 2);
        float s2[2];
#pragma unroll
        for (int k = 0; k < 2; k++) {
            const float keep = h2 ? s4[k + 2] : s4[k];
            const float send = h2 ? s4[k] : s4[k + 2];
            s2[k] = keep + __shfl_xor_sync(0xffffffffu, send, 2);
        }
        const bool h1 = (lane & 1);
        const float keep = h1 ? s2[1] : s2[0];
        const float send = h1 ? s2[0] : s2[1];
        const float tot = keep + __shfl_xor_sync(0xffffffffu, send, 1);

        yh[t0 + lane] = __float2half_rn(fmaf(Dd, uv, tot));
    }
}

// ---------------------------------------------------------------------------
extern "C" void kernel_launch(void* const* d_in, const int* in_sizes, int n_in,
                              void* d_out, int out_size)
{
    const float* x     = (const float*)d_in[0];
    const float* W_in  = (const float*)d_in[1];
    const float* b_in  = (const float*)d_in[2];
    const float* A_log = (const float*)d_in[3];
    const float* B     = (const float*)d_in[4];
    const float* C     = (const float*)d_in[5];
    const float* D     = (const float*)d_in[6];
    const float* dt    = (const float*)d_in[7];
    const float* W_out = (const float*)d_in[8];
    const float* b_out = (const float*)d_in[9];
    float* out = (float*)d_out;

    static bool attr_done = false;
    if (!attr_done) {
        cudaFuncSetAttribute(gemm_mma1, cudaFuncAttributeMaxDynamicSharedMemorySize, SMEM_BYTES);
        cudaFuncSetAttribute(gemm_mma2, cudaFuncAttributeMaxDynamicSharedMemorySize, SMEM_BYTES);
        attr_done = true;
    }

    __half *p_ah, *p_wh;
    cudaGetSymbolAddress((void**)&p_ah, g_ah);
    cudaGetSymbolAddress((void**)&p_wh, g_wh);

    // 1) convert: x -> hi, weights -> hi (single launch)
    {
        const int total = N4_X + 2 * N4_W;
        convert_all<<<(total + 255) / 256, 256>>>(x, W_in, W_out, p_ah, p_wh);
    }

    // 2) in_proj: D[d, token] -> g_u[b][d][l]   (grid 32x4 = 128 CTAs, 1 wave)
    {
        dim3 g(MTOT / 256, DMODEL / 128);
        gemm_mma1<<<g, NTHREADS, SMEM_BYTES>>>(p_wh, p_ah, b_in);
    }

    // 3) SSM recurrence: g_u -> g_yh  (2 segments/seq, 1024 CTAs x 128 thr)
    s4_scan<<<BATCH * DMODEL * 2 / 4, 128>>>(A_log, B, C, D, dt);

    // 4) out_proj: yh (trans) @ W_out_h^T -> out (grid 2x64 = 128 CTAs, 1 wave)
    {
        dim3 g(DMODEL / 256, MTOT / 128);
        gemm_mma2<<<g, NTHREADS, SMEM_BYTES>>>(p_wh + DMODEL * DMODEL, b_out, out);
    }
}